// round 12
// baseline (speedup 1.0000x reference)
#include <cuda_runtime.h>
#include <cuda_bf16.h>
#include <math.h>
#include <cstdint>

#define BATCH 4096
#define T 64
#define HID 256
#define INDIM 192

// ---------------- device scratch ----------------
__device__ float g_proj[3][(size_t)T * BATCH * HID];              // input projections
__device__ __nv_bfloat16 g_wbf[3][2][HID * HID];                  // W_rec hi/lo bf16
__device__ __nv_bfloat16 g_wbf_in[3][2][HID * INDIM];             // W_in hi/lo bf16
__device__ float g_hfin[BATCH * HID];                             // final h (fp32) for head

// ---------------- helpers ----------------
__device__ __forceinline__ uint32_t smem_to_u32(const void* p) {
    uint32_t a;
    asm("{ .reg .u64 t; cvta.to.shared.u64 t, %1; cvt.u32.u64 %0, t; }" : "=r"(a) : "l"(p));
    return a;
}
__device__ __forceinline__ uint32_t lds32(uint32_t a) {
    uint32_t v;
    asm volatile("ld.shared.b32 %0, [%1];" : "=r"(v) : "r"(a));
    return v;
}
__device__ __forceinline__ void sts32(uint32_t a, uint32_t v) {
    asm volatile("st.shared.b32 [%0], %1;" :: "r"(a), "r"(v));
}
__device__ __forceinline__ void sts64(uint32_t a, uint32_t v0, uint32_t v1) {
    asm volatile("st.shared.v2.b32 [%0], {%1, %2};" :: "r"(a), "r"(v0), "r"(v1));
}
#define CP_ASYNC16(dst, src) \
    asm volatile("cp.async.cg.shared.global [%0], [%1], 16;" :: "r"(dst), "l"(src))
#define CP_COMMIT() asm volatile("cp.async.commit_group;" ::: "memory")
#define CP_WAIT(n)  asm volatile("cp.async.wait_group %0;" :: "n"(n) : "memory")

// bf16 mma: D(16x8 fp32) += A(16x16) * B(16x8)
__device__ __forceinline__ void mma_bf16(float* c, const uint32_t* a, const uint32_t* b) {
    asm volatile(
        "mma.sync.aligned.m16n8k16.row.col.f32.bf16.bf16.f32 "
        "{%0,%1,%2,%3}, {%4,%5,%6,%7}, {%8,%9}, {%0,%1,%2,%3};"
        : "+f"(c[0]), "+f"(c[1]), "+f"(c[2]), "+f"(c[3])
        : "r"(a[0]), "r"(a[1]), "r"(a[2]), "r"(a[3]), "r"(b[0]), "r"(b[1]));
}

__device__ __forceinline__ uint32_t pack_hi2(float x0, float x1) {
    __nv_bfloat162 h = __halves2bfloat162(__float2bfloat16(x0), __float2bfloat16(x1));
    return *(uint32_t*)&h;
}
__device__ __forceinline__ uint32_t pack_lo2(float x0, float x1) {
    __nv_bfloat16 h0 = __float2bfloat16(x0);
    __nv_bfloat16 h1 = __float2bfloat16(x1);
    __nv_bfloat162 l = __halves2bfloat162(
        __float2bfloat16(x0 - __bfloat162float(h0)),
        __float2bfloat16(x1 - __bfloat162float(h1)));
    return *(uint32_t*)&l;
}

// ---------------- W split prep: fp32 -> bf16 hi + lo ----------------
__global__ void wprep_kernel(const float* __restrict__ wfr, const float* __restrict__ wgr,
                             const float* __restrict__ wtr,
                             const float* __restrict__ wfi, const float* __restrict__ wgi,
                             const float* __restrict__ wti) {
    int i = blockIdx.x * blockDim.x + threadIdx.x;
    if (i < HID * HID) {
        const float* ws[3] = {wfr, wgr, wtr};
        #pragma unroll
        for (int m = 0; m < 3; m++) {
            float x = ws[m][i];
            __nv_bfloat16 h = __float2bfloat16(x);
            g_wbf[m][0][i] = h;
            g_wbf[m][1][i] = __float2bfloat16(x - __bfloat162float(h));
        }
    }
    if (i < HID * INDIM) {
        const float* ws[3] = {wfi, wgi, wti};
        #pragma unroll
        for (int m = 0; m < 3; m++) {
            float x = ws[m][i];
            __nv_bfloat16 h = __float2bfloat16(x);
            g_wbf_in[m][0][i] = h;
            g_wbf_in[m][1][i] = __float2bfloat16(x - __bfloat162float(h));
        }
    }
}

// =========================================================================
// proj kernel via mma.sync (unchanged, proven): 512 threads, grid (2048, 4)
// =========================================================================
#define NTHREADS 512
#define PITCHB 144
#define A_BYTES (256 * PITCHB)
#define B_BYTES (384 * PITCHB)
#define BUF_BYTES (A_BYTES + B_BYTES)
#define PROJ_SMEM (2 * BUF_BYTES)

#define COMPUTE_CHUNK(bb)                                                        \
    do {                                                                         \
        const uint32_t Abase = sbase + (bb) * BUF_BYTES;                         \
        const uint32_t Bbase = Abase + A_BYTES;                                  \
        _Pragma("unroll")                                                        \
        for (int q = 0; q < 4; q++) {                                            \
            const uint32_t koff = q * 32 + tig * 4;                              \
            uint32_t ahi[2][4], alo[2][4];                                       \
            _Pragma("unroll")                                                    \
            for (int f = 0; f < 2; f++) {                                        \
                uint32_t rh = Abase + (uint32_t)((m0w + f * 16 + group) * PITCHB) + koff; \
                ahi[f][0] = lds32(rh);                                           \
                ahi[f][1] = lds32(rh + 8 * PITCHB);                              \
                ahi[f][2] = lds32(rh + 16);                                      \
                ahi[f][3] = lds32(rh + 8 * PITCHB + 16);                         \
                uint32_t rl = rh + 128 * PITCHB;                                 \
                alo[f][0] = lds32(rl);                                           \
                alo[f][1] = lds32(rl + 8 * PITCHB);                              \
                alo[f][2] = lds32(rl + 16);                                      \
                alo[f][3] = lds32(rl + 8 * PITCHB + 16);                         \
            }                                                                    \
            _Pragma("unroll")                                                    \
            for (int mat = 0; mat < 3; mat++) {                                  \
                uint32_t bh[2][2], bl[2][2];                                     \
                _Pragma("unroll")                                                \
                for (int j = 0; j < 2; j++) {                                    \
                    uint32_t rbh = Bbase +                                       \
                        (uint32_t)(((mat * 2) * 64 + n0w + j * 8 + group) * PITCHB) + koff; \
                    bh[j][0] = lds32(rbh); bh[j][1] = lds32(rbh + 16);           \
                    uint32_t rbl = rbh + 64 * PITCHB;                            \
                    bl[j][0] = lds32(rbl); bl[j][1] = lds32(rbl + 16);           \
                }                                                                \
                _Pragma("unroll")                                                \
                for (int j = 0; j < 2; j++)                                      \
                    { mma_bf16(acc[mat][0][j], ahi[0], bh[j]);                   \
                      mma_bf16(acc[mat][1][j], ahi[1], bh[j]); }                 \
                _Pragma("unroll")                                                \
                for (int j = 0; j < 2; j++)                                      \
                    { mma_bf16(acc[mat][0][j], ahi[0], bl[j]);                   \
                      mma_bf16(acc[mat][1][j], ahi[1], bl[j]); }                 \
                _Pragma("unroll")                                                \
                for (int j = 0; j < 2; j++)                                      \
                    { mma_bf16(acc[mat][0][j], alo[0], bh[j]);                   \
                      mma_bf16(acc[mat][1][j], alo[1], bh[j]); }                 \
            }                                                                    \
        }                                                                        \
    } while (0)

__global__ __launch_bounds__(NTHREADS, 1) void proj_mma_kernel(
    const float* __restrict__ x,
    const float* __restrict__ bfa, const float* __restrict__ bfb,
    const float* __restrict__ bga, const float* __restrict__ bgb,
    const float* __restrict__ bta, const float* __restrict__ btb)
{
    extern __shared__ char sm[];
    const uint32_t sbase = smem_to_u32(sm);

    const int tid   = threadIdx.x;
    const int warp  = tid >> 5;
    const int lane  = tid & 31;
    const int group = lane >> 2;
    const int tig   = lane & 3;
    const int m0    = blockIdx.x * 128;
    const int n0    = blockIdx.y * 64;
    const int m0w   = (warp & 3) * 32;
    const int n0w   = (warp >> 2) * 16;
    const int tq    = m0 >> 12;
    const int bq0   = m0 & 4095;

    float acc[3][2][2][4] = {};

    auto stageA = [&](int chunk, int bb) {
        const uint32_t dstb = sbase + bb * BUF_BYTES;
        #pragma unroll
        for (int j = 0; j < 4; j++) {
            int u   = tid + j * NTHREADS;
            int row = u >> 4;
            int f4  = u & 15;
            float4 v = *(const float4*)&x[((((size_t)(bq0 + row) * 3 + chunk) << 6) + tq) * 64 + f4 * 4];
            uint32_t base = dstb + (uint32_t)(row * PITCHB + f4 * 8);
            sts64(base, pack_hi2(v.x, v.y), pack_hi2(v.z, v.w));
            sts64(base + 128 * PITCHB, pack_lo2(v.x, v.y), pack_lo2(v.z, v.w));
        }
    };
    auto stageB = [&](int chunk, int bb) {
        const int kc0 = chunk * 64;
        const uint32_t dstb = sbase + bb * BUF_BYTES + A_BYTES;
        #pragma unroll
        for (int j = 0; j < 6; j++) {
            int u = tid + j * NTHREADS;
            int rg = u >> 9, row = (u >> 3) & 63, kb = u & 7;
            int mat = rg >> 1, sp = rg & 1;
            const __nv_bfloat16* src =
                &g_wbf_in[mat][sp][(size_t)(n0 + row) * INDIM + kc0 + kb * 8];
            uint32_t dst = dstb + (uint32_t)((rg * 64 + row) * PITCHB + kb * 16);
            CP_ASYNC16(dst, src);
        }
    };

    stageB(0, 0); CP_COMMIT();
    stageA(0, 0);
    #pragma unroll 1
    for (int c = 0; c < 3; c++) {
        if (c < 2) {
            stageB(c + 1, (c + 1) & 1); CP_COMMIT();
            stageA(c + 1, (c + 1) & 1);
            CP_WAIT(1);
        } else {
            CP_WAIT(0);
        }
        __syncthreads();
        COMPUTE_CHUNK(c & 1);
        __syncthreads();
    }

    const float* inb[3]  = {bfa, bga, bta};
    const float* hbb[3]  = {bfb, bgb, btb};
    #pragma unroll
    for (int f = 0; f < 2; f++) {
        #pragma unroll
        for (int hh = 0; hh < 2; hh++) {
            const int m = m0w + f * 16 + group + hh * 8;
            const size_t obase = (size_t)(m0 + m) * HID;
            #pragma unroll
            for (int j = 0; j < 2; j++) {
                const int jabs = n0 + n0w + j * 8 + tig * 2;
                #pragma unroll
                for (int mat = 0; mat < 3; mat++) {
                    float2 bi = *(const float2*)&inb[mat][jabs];
                    float2 bh2 = *(const float2*)&hbb[mat][jabs];
                    float2 o;
                    o.x = acc[mat][f][j][hh * 2]     + bi.x + bh2.x;
                    o.y = acc[mat][f][j][hh * 2 + 1] + bi.y + bh2.y;
                    *(float2*)&g_proj[mat][obase + jabs] = o;
                }
            }
        }
    }
}

// =========================================================================
// persistent recurrence, communication-free decomposition:
// CTA = 32 batch rows x ALL 256 cols x 3 mats; h resident in smem as the
// next step's A fragments (rewritten in place by the epilogue).
// W (hi/lo) streamed from L2 in 8 x 96KB double-buffered k-chunks.
// 128 independent CTAs, 1024 threads (32 warps; warp w -> cols w*8..w*8+7).
// =========================================================================
#define STHREADS 1024
#define KCH 32
#define NCHUNK 8
#define B_CH_BYTES 98304              // 1536 virtual rows x 64 B
#define A_RES_BYTES 32768             // 4 kchunks x 2 splits x 32 rows x 128 B
#define PERS_SMEM (2 * B_CH_BYTES + A_RES_BYTES + 128)

__global__ __launch_bounds__(STHREADS, 1) void ltc_persistent_kernel()
{
    extern __shared__ char sm[];
    const uint32_t sB = (smem_to_u32(sm) + 127u) & ~127u;
    const uint32_t sA = sB + 2 * B_CH_BYTES;

    const int tid   = threadIdx.x;
    const int warp  = tid >> 5;
    const int lane  = tid & 31;
    const int group = lane >> 2;
    const int tig   = lane & 3;
    const int b0    = blockIdx.x * 32;

    // h0 = 0: zero the resident A region
    for (int i = tid; i < A_RES_BYTES / 16; i += STHREADS)
        asm volatile("st.shared.v4.b32 [%0], {%1,%1,%1,%1};"
                     :: "r"(sA + (uint32_t)(i * 16)), "r"(0u));
    __syncthreads();

    // h carried in fp32 registers for the epilogue update
    // [mt][hh][e] -> row = mt*16 + group + hh*8, col = warp*8 + tig*2 + e
    float hvreg[2][2][2] = {};

    const uint32_t swzB = (uint32_t)(((group >> 1) & 3) << 4);
    const int ccol = (warp << 3) + tig * 2;

    // stream one 32-wide K chunk of all W hi/lo into buffer bb
    auto stageB = [&](int c, int bb) {
        const uint32_t dstb = sB + bb * B_CH_BYTES;
        #pragma unroll
        for (int j = 0; j < 6; j++) {
            int u  = tid + j * STHREADS;        // 0..6143 16B units
            int rr = u >> 2, kb = u & 3;
            int mat = rr >> 9, sp = (rr >> 8) & 1, ncol = rr & 255;
            const __nv_bfloat16* src =
                &g_wbf[mat][sp][(size_t)ncol * HID + c * KCH + kb * 8];
            uint32_t dst = dstb + (uint32_t)(rr * 64 +
                            ((kb * 16) ^ (((rr >> 1) & 3) << 4)));
            CP_ASYNC16(dst, src);
        }
    };

    #pragma unroll 1
    for (int t = 0; t < T; t++) {
        float acc[3][2][4] = {};

        stageB(0, 0); CP_COMMIT();
        #pragma unroll 1
        for (int c = 0; c < NCHUNK; c++) {
            if (c < NCHUNK - 1) { stageB(c + 1, (c + 1) & 1); CP_COMMIT(); CP_WAIT(1); }
            else CP_WAIT(0);
            __syncthreads();
            const uint32_t Bb = sB + (c & 1) * B_CH_BYTES;
            #pragma unroll
            for (int q2 = 0; q2 < 2; q2++) {
                const int kt = c * 2 + q2;
                const uint32_t pA = (uint32_t)(((kt & 3) * 32 + tig * 4) ^ (group << 4));
                uint32_t ahi[2][4], alo[2][4];
                #pragma unroll
                for (int mt = 0; mt < 2; mt++) {
                    uint32_t rh = sA + (uint32_t)((kt >> 2) * 8192 +
                                                  (mt * 16 + group) * 128) + pA;
                    ahi[mt][0] = lds32(rh);        ahi[mt][1] = lds32(rh + 1024);
                    ahi[mt][2] = lds32(rh ^ 16u);  ahi[mt][3] = lds32((rh + 1024) ^ 16u);
                    uint32_t rl = rh + 4096;
                    alo[mt][0] = lds32(rl);        alo[mt][1] = lds32(rl + 1024);
                    alo[mt][2] = lds32(rl ^ 16u);  alo[mt][3] = lds32((rl + 1024) ^ 16u);
                }
                const uint32_t pBq = (uint32_t)(q2 * 32 + tig * 4) ^ swzB;
                #pragma unroll
                for (int mat = 0; mat < 3; mat++) {
                    const uint32_t rowh = (uint32_t)((mat * 2) * 256 + (warp << 3) + group);
                    uint32_t adrh = Bb + rowh * 64 + pBq;
                    uint32_t bh[2] = { lds32(adrh), lds32(adrh ^ 16u) };
                    uint32_t adrl = adrh + 256 * 64;
                    uint32_t bl[2] = { lds32(adrl), lds32(adrl ^ 16u) };
                    mma_bf16(acc[mat][0], ahi[0], bh);
                    mma_bf16(acc[mat][1], ahi[1], bh);
                    mma_bf16(acc[mat][0], ahi[0], bl);
                    mma_bf16(acc[mat][1], ahi[1], bl);
                    mma_bf16(acc[mat][0], alo[0], bh);
                    mma_bf16(acc[mat][1], alo[1], bh);
                }
            }
            __syncthreads();
        }

        // ---- fused LTC epilogue: update h, rewrite resident A in place ----
        #pragma unroll
        for (int mt = 0; mt < 2; mt++) {
            #pragma unroll
            for (int hh = 0; hh < 2; hh++) {
                const int r = mt * 16 + group + hh * 8;
                const int b = b0 + r;
                const size_t pbase = ((size_t)t * BATCH + b) * HID + ccol;
                float2 pf = *(const float2*)&g_proj[0][pbase];
                float2 pg = *(const float2*)&g_proj[1][pbase];
                float2 pt = *(const float2*)&g_proj[2][pbase];
                float o2[2];
                #pragma unroll
                for (int e = 0; e < 2; e++) {
                    float rf = acc[0][mt][hh * 2 + e];
                    float rg = acc[1][mt][hh * 2 + e];
                    float rt = acc[2][mt][hh * 2 + e];
                    float pfe = e ? pf.y : pf.x;
                    float pge = e ? pg.y : pg.x;
                    float pte = e ? pt.y : pt.x;
                    float hve = hvreg[mt][hh][e];
                    float e2 = __expf(2.f * (pfe + rf));
                    float cand = __fdividef(e2 - 1.f, e2 + 1.f);
                    float gate = __fdividef(1.f, 1.f + __expf(-(pge + rg)));
                    float tau  = 0.5f + 1.5f * __fdividef(1.f, 1.f + __expf(-(pte + rt)));
                    float hn = hve + __fdividef(gate * cand - hve, tau);
                    float e2h = __expf(2.f * hn);
                    o2[e] = __fdividef(e2h - 1.f, e2h + 1.f);
                    hvreg[mt][hh][e] = o2[e];
                }
                // write next-step A fragments (bf16 hi/lo) in place
                const uint32_t kb = (uint32_t)(warp & 7);
                uint32_t adst = sA + (uint32_t)((warp >> 3) * 8192 + r * 128) +
                                ((kb * 16) ^ ((uint32_t)(r & 7) << 4)) +
                                (uint32_t)(tig * 4);
                sts32(adst, pack_hi2(o2[0], o2[1]));
                sts32(adst + 4096, pack_lo2(o2[0], o2[1]));
                if (t == T - 1)
                    *(float2*)&g_hfin[(size_t)b * HID + ccol] = make_float2(o2[0], o2[1]);
            }
        }
        __syncthreads();
    }
}

// ---------------- head: [4096,256] x [256,10] + bias ----------------
__global__ void head_kernel(const float* __restrict__ hw,
                            const float* __restrict__ hb,
                            float* __restrict__ out)
{
    int gwarp = (blockIdx.x * blockDim.x + threadIdx.x) >> 5;
    int lane  = threadIdx.x & 31;
    if (gwarp >= BATCH * 10) return;
    int o = gwarp % 10;
    int b = gwarp / 10;
    float s = 0.f;
    #pragma unroll
    for (int k = lane; k < HID; k += 32)
        s += g_hfin[(size_t)b * HID + k] * hw[o * HID + k];
    #pragma unroll
    for (int off = 16; off; off >>= 1)
        s += __shfl_down_sync(0xffffffffu, s, off);
    if (lane == 0) out[b * 10 + o] = s + hb[o];
}

extern "C" void kernel_launch(void* const* d_in, const int* in_sizes, int n_in,
                              void* d_out, int out_size)
{
    const float* x      = (const float*)d_in[0];
    const float* ffw    = (const float*)d_in[1];
    const float* ffb    = (const float*)d_in[2];
    const float* ffrw   = (const float*)d_in[3];
    const float* ffbias = (const float*)d_in[4];
    const float* gw     = (const float*)d_in[5];
    const float* gb     = (const float*)d_in[6];
    const float* grw    = (const float*)d_in[7];
    const float* gbias  = (const float*)d_in[8];
    const float* tw     = (const float*)d_in[9];
    const float* tb     = (const float*)d_in[10];
    const float* trw    = (const float*)d_in[11];
    const float* tbias  = (const float*)d_in[12];
    const float* hw     = (const float*)d_in[13];
    const float* hb     = (const float*)d_in[14];
    float* out = (float*)d_out;

    cudaFuncSetAttribute(proj_mma_kernel,
                         cudaFuncAttributeMaxDynamicSharedMemorySize, PROJ_SMEM);
    cudaFuncSetAttribute(ltc_persistent_kernel,
                         cudaFuncAttributeMaxDynamicSharedMemorySize, PERS_SMEM);

    // W (recurrent + input) -> bf16 hi/lo scratch
    wprep_kernel<<<(HID * HID + 255) / 256, 256>>>(ffrw, grw, trw, ffw, gw, tw);

    // all input projections on the tensor pipe
    dim3 pgrid((T * BATCH) / 128, HID / 64);
    proj_mma_kernel<<<pgrid, NTHREADS, PROJ_SMEM>>>(x, ffb, ffbias, gb, gbias, tb, tbias);

    // all 64 LTC steps: communication-free persistent kernel
    ltc_persistent_kernel<<<BATCH / 32, STHREADS, PERS_SMEM>>>();

    // classifier head
    head_kernel<<<(BATCH * 10 * 32 + 255) / 256, 256>>>(hw, hb, out);
}

// round 13
// speedup vs baseline: 1.0758x; 1.0758x over previous
#include <cuda_runtime.h>
#include <cuda_bf16.h>
#include <math.h>
#include <cstdint>

#define BATCH 4096
#define T 64
#define HID 256
#define INDIM 192
#define NCTA 128

// ---------------- device scratch ----------------
__device__ float g_proj[3][(size_t)T * BATCH * HID];              // input projections
__device__ __nv_bfloat16 g_wbf[3][2][HID * HID];                  // W_rec hi/lo bf16
__device__ __nv_bfloat16 g_wbf_in[3][2][HID * INDIM];             // W_in hi/lo bf16
__device__ __nv_bfloat16 g_hbf[2][2][(size_t)BATCH * HID];        // h hi/lo bf16 ping-pong
__device__ unsigned g_bar_count;
__device__ unsigned g_bar_phase;

// ---------------- helpers ----------------
__device__ __forceinline__ uint32_t smem_to_u32(const void* p) {
    uint32_t a;
    asm("{ .reg .u64 t; cvta.to.shared.u64 t, %1; cvt.u32.u64 %0, t; }" : "=r"(a) : "l"(p));
    return a;
}
__device__ __forceinline__ uint32_t lds32(uint32_t a) {
    uint32_t v;
    asm volatile("ld.shared.b32 %0, [%1];" : "=r"(v) : "r"(a));
    return v;
}
__device__ __forceinline__ void sts64(uint32_t a, uint32_t v0, uint32_t v1) {
    asm volatile("st.shared.v2.b32 [%0], {%1, %2};" :: "r"(a), "r"(v0), "r"(v1));
}
__device__ __forceinline__ uint32_t ldcg_u32(const void* p) {
    uint32_t v;
    asm volatile("ld.global.cg.u32 %0, [%1];" : "=r"(v) : "l"(p));
    return v;
}
#define CP_ASYNC16(dst, src) \
    asm volatile("cp.async.cg.shared.global [%0], [%1], 16;" :: "r"(dst), "l"(src))
#define CP_COMMIT() asm volatile("cp.async.commit_group;" ::: "memory")
#define CP_WAIT(n)  asm volatile("cp.async.wait_group %0;" :: "n"(n) : "memory")

// bf16 mma: D(16x8 fp32) += A(16x16) * B(16x8)
__device__ __forceinline__ void mma_bf16(float* c, const uint32_t* a, const uint32_t* b) {
    asm volatile(
        "mma.sync.aligned.m16n8k16.row.col.f32.bf16.bf16.f32 "
        "{%0,%1,%2,%3}, {%4,%5,%6,%7}, {%8,%9}, {%0,%1,%2,%3};"
        : "+f"(c[0]), "+f"(c[1]), "+f"(c[2]), "+f"(c[3])
        : "r"(a[0]), "r"(a[1]), "r"(a[2]), "r"(a[3]), "r"(b[0]), "r"(b[1]));
}

__device__ __forceinline__ uint32_t pack_hi2(float x0, float x1) {
    __nv_bfloat162 h = __halves2bfloat162(__float2bfloat16(x0), __float2bfloat16(x1));
    return *(uint32_t*)&h;
}
__device__ __forceinline__ uint32_t pack_lo2(float x0, float x1) {
    __nv_bfloat16 h0 = __float2bfloat16(x0);
    __nv_bfloat16 h1 = __float2bfloat16(x1);
    __nv_bfloat162 l = __halves2bfloat162(
        __float2bfloat16(x0 - __bfloat162float(h0)),
        __float2bfloat16(x1 - __bfloat162float(h1)));
    return *(uint32_t*)&l;
}

// ---------------- zero h0 + barrier reset ----------------
__global__ void zero_h_kernel() {
    int i = blockIdx.x * blockDim.x + threadIdx.x;
    if (i < BATCH * HID) {
        g_hbf[0][0][i] = __float2bfloat16(0.f);
        g_hbf[0][1][i] = __float2bfloat16(0.f);
    }
    if (i == 0) { g_bar_count = 0u; g_bar_phase = 0u; }
}

// ---------------- W split prep: fp32 -> bf16 hi + lo ----------------
__global__ void wprep_kernel(const float* __restrict__ wfr, const float* __restrict__ wgr,
                             const float* __restrict__ wtr,
                             const float* __restrict__ wfi, const float* __restrict__ wgi,
                             const float* __restrict__ wti) {
    int i = blockIdx.x * blockDim.x + threadIdx.x;
    if (i < HID * HID) {
        const float* ws[3] = {wfr, wgr, wtr};
        #pragma unroll
        for (int m = 0; m < 3; m++) {
            float x = ws[m][i];
            __nv_bfloat16 h = __float2bfloat16(x);
            g_wbf[m][0][i] = h;
            g_wbf[m][1][i] = __float2bfloat16(x - __bfloat162float(h));
        }
    }
    if (i < HID * INDIM) {
        const float* ws[3] = {wfi, wgi, wti};
        #pragma unroll
        for (int m = 0; m < 3; m++) {
            float x = ws[m][i];
            __nv_bfloat16 h = __float2bfloat16(x);
            g_wbf_in[m][0][i] = h;
            g_wbf_in[m][1][i] = __float2bfloat16(x - __bfloat162float(h));
        }
    }
}

// =========================================================================
// proj kernel via mma.sync: 512 threads.
// GRID AXES SWAPPED vs R11: blockIdx.x = n-tile (4), blockIdx.y = m-tile (2048)
// so the 4 blocks sharing one x A-tile are adjacent in schedule -> L2 reuse.
// =========================================================================
#define NTHREADS 512
#define PITCHB 144
#define A_BYTES (256 * PITCHB)
#define B_BYTES (384 * PITCHB)
#define BUF_BYTES (A_BYTES + B_BYTES)
#define PROJ_SMEM (2 * BUF_BYTES)

#define COMPUTE_CHUNK(bb)                                                        \
    do {                                                                         \
        const uint32_t Abase = sbase + (bb) * BUF_BYTES;                         \
        const uint32_t Bbase = Abase + A_BYTES;                                  \
        _Pragma("unroll")                                                        \
        for (int q = 0; q < 4; q++) {                                            \
            const uint32_t koff = q * 32 + tig * 4;                              \
            uint32_t ahi[2][4], alo[2][4];                                       \
            _Pragma("unroll")                                                    \
            for (int f = 0; f < 2; f++) {                                        \
                uint32_t rh = Abase + (uint32_t)((m0w + f * 16 + group) * PITCHB) + koff; \
                ahi[f][0] = lds32(rh);                                           \
                ahi[f][1] = lds32(rh + 8 * PITCHB);                              \
                ahi[f][2] = lds32(rh + 16);                                      \
                ahi[f][3] = lds32(rh + 8 * PITCHB + 16);                         \
                uint32_t rl = rh + 128 * PITCHB;                                 \
                alo[f][0] = lds32(rl);                                           \
                alo[f][1] = lds32(rl + 8 * PITCHB);                              \
                alo[f][2] = lds32(rl + 16);                                      \
                alo[f][3] = lds32(rl + 8 * PITCHB + 16);                         \
            }                                                                    \
            _Pragma("unroll")                                                    \
            for (int mat = 0; mat < 3; mat++) {                                  \
                uint32_t bh[2][2], bl[2][2];                                     \
                _Pragma("unroll")                                                \
                for (int j = 0; j < 2; j++) {                                    \
                    uint32_t rbh = Bbase +                                       \
                        (uint32_t)(((mat * 2) * 64 + n0w + j * 8 + group) * PITCHB) + koff; \
                    bh[j][0] = lds32(rbh); bh[j][1] = lds32(rbh + 16);           \
                    uint32_t rbl = rbh + 64 * PITCHB;                            \
                    bl[j][0] = lds32(rbl); bl[j][1] = lds32(rbl + 16);           \
                }                                                                \
                _Pragma("unroll")                                                \
                for (int j = 0; j < 2; j++)                                      \
                    { mma_bf16(acc[mat][0][j], ahi[0], bh[j]);                   \
                      mma_bf16(acc[mat][1][j], ahi[1], bh[j]); }                 \
                _Pragma("unroll")                                                \
                for (int j = 0; j < 2; j++)                                      \
                    { mma_bf16(acc[mat][0][j], ahi[0], bl[j]);                   \
                      mma_bf16(acc[mat][1][j], ahi[1], bl[j]); }                 \
                _Pragma("unroll")                                                \
                for (int j = 0; j < 2; j++)                                      \
                    { mma_bf16(acc[mat][0][j], alo[0], bh[j]);                   \
                      mma_bf16(acc[mat][1][j], alo[1], bh[j]); }                 \
            }                                                                    \
        }                                                                        \
    } while (0)

__global__ __launch_bounds__(NTHREADS, 1) void proj_mma_kernel(
    const float* __restrict__ x,
    const float* __restrict__ bfa, const float* __restrict__ bfb,
    const float* __restrict__ bga, const float* __restrict__ bgb,
    const float* __restrict__ bta, const float* __restrict__ btb)
{
    extern __shared__ char sm[];
    const uint32_t sbase = smem_to_u32(sm);

    const int tid   = threadIdx.x;
    const int warp  = tid >> 5;
    const int lane  = tid & 31;
    const int group = lane >> 2;
    const int tig   = lane & 3;
    const int m0    = blockIdx.y * 128;     // m-tile on Y (2048)
    const int n0    = blockIdx.x * 64;      // n-tile on X (4) -> siblings adjacent
    const int m0w   = (warp & 3) * 32;
    const int n0w   = (warp >> 2) * 16;
    const int tq    = m0 >> 12;
    const int bq0   = m0 & 4095;

    float acc[3][2][2][4] = {};

    auto stageA = [&](int chunk, int bb) {
        const uint32_t dstb = sbase + bb * BUF_BYTES;
        #pragma unroll
        for (int j = 0; j < 4; j++) {
            int u   = tid + j * NTHREADS;
            int row = u >> 4;
            int f4  = u & 15;
            float4 v = *(const float4*)&x[((((size_t)(bq0 + row) * 3 + chunk) << 6) + tq) * 64 + f4 * 4];
            uint32_t base = dstb + (uint32_t)(row * PITCHB + f4 * 8);
            sts64(base, pack_hi2(v.x, v.y), pack_hi2(v.z, v.w));
            sts64(base + 128 * PITCHB, pack_lo2(v.x, v.y), pack_lo2(v.z, v.w));
        }
    };
    auto stageB = [&](int chunk, int bb) {
        const int kc0 = chunk * 64;
        const uint32_t dstb = sbase + bb * BUF_BYTES + A_BYTES;
        #pragma unroll
        for (int j = 0; j < 6; j++) {
            int u = tid + j * NTHREADS;
            int rg = u >> 9, row = (u >> 3) & 63, kb = u & 7;
            int mat = rg >> 1, sp = rg & 1;
            const __nv_bfloat16* src =
                &g_wbf_in[mat][sp][(size_t)(n0 + row) * INDIM + kc0 + kb * 8];
            uint32_t dst = dstb + (uint32_t)((rg * 64 + row) * PITCHB + kb * 16);
            CP_ASYNC16(dst, src);
        }
    };

    stageB(0, 0); CP_COMMIT();
    stageA(0, 0);
    #pragma unroll 1
    for (int c = 0; c < 3; c++) {
        if (c < 2) {
            stageB(c + 1, (c + 1) & 1); CP_COMMIT();
            stageA(c + 1, (c + 1) & 1);
            CP_WAIT(1);
        } else {
            CP_WAIT(0);
        }
        __syncthreads();
        COMPUTE_CHUNK(c & 1);
        __syncthreads();
    }

    const float* inb[3]  = {bfa, bga, bta};
    const float* hbb[3]  = {bfb, bgb, btb};
    #pragma unroll
    for (int f = 0; f < 2; f++) {
        #pragma unroll
        for (int hh = 0; hh < 2; hh++) {
            const int m = m0w + f * 16 + group + hh * 8;
            const size_t obase = (size_t)(m0 + m) * HID;
            #pragma unroll
            for (int j = 0; j < 2; j++) {
                const int jabs = n0 + n0w + j * 8 + tig * 2;
                #pragma unroll
                for (int mat = 0; mat < 3; mat++) {
                    float2 bi = *(const float2*)&inb[mat][jabs];
                    float2 bh2 = *(const float2*)&hbb[mat][jabs];
                    float2 o;
                    o.x = acc[mat][f][j][hh * 2]     + bi.x + bh2.x;
                    o.y = acc[mat][f][j][hh * 2 + 1] + bi.y + bh2.y;
                    *(float2*)&g_proj[mat][obase + jabs] = o;
                }
            }
        }
    }
}

// =========================================================================
// persistent recurrence (R11, best known): all 64 steps, W resident in smem,
// h in registers. 1024 threads (32 warps, 8m x 4n), CTA 256 rows x 32 cols.
// =========================================================================
#define STHREADS 1024
#define W_SM_BYTES 98304
#define A_SM_BYTES 65536
#define PERS_SMEM (W_SM_BYTES + 2 * A_SM_BYTES + 128)

__global__ __launch_bounds__(STHREADS, 1) void ltc_persistent_kernel()
{
    extern __shared__ char sm[];
    const uint32_t sW = (smem_to_u32(sm) + 127u) & ~127u;
    const uint32_t sA = sW + W_SM_BYTES;

    const int tid   = threadIdx.x;
    const int warp  = tid >> 5;
    const int lane  = tid & 31;
    const int group = lane >> 2;
    const int tig   = lane & 3;
    const int bx    = blockIdx.x;
    const int b0    = (bx & 15) * 256;
    const int n0    = (bx >> 4) * 32;
    const int m0w   = (warp & 7) * 32;     // 8 m-warps x 32 rows
    const int n0w   = (warp >> 3) * 8;     // 4 n-warps x 8 cols

    // ---- load W once: 6 regions x 32 rows x 512B, XOR-swizzled ----
    #pragma unroll
    for (int j = 0; j < 6; j++) {
        int u   = tid + j * STHREADS;
        int rg  = u >> 10;
        int rem = u & 1023;
        int row = rem >> 5;
        int kb  = rem & 31;
        int mat = rg >> 1, sp = rg & 1;
        const __nv_bfloat16* src = &g_wbf[mat][sp][(size_t)(n0 + row) * HID + kb * 8];
        uint32_t dst = sW + (uint32_t)(rg * 16384 + row * 512 + ((kb * 16) ^ ((row & 7) << 4)));
        CP_ASYNC16(dst, src);
    }
    CP_COMMIT(); CP_WAIT(0);
    __syncthreads();

    // h state in registers: [f][hh][e] -> b = b0+m0w+f*16+group+hh*8,
    //                                     col = n0+n0w+tig*2+e
    float hvreg[2][2][2] = {};

    #pragma unroll 1
    for (int t = 0; t < T; t++) {
        const __nv_bfloat16* __restrict__ hbf_hi = g_hbf[t & 1][0];
        const __nv_bfloat16* __restrict__ hbf_lo = g_hbf[t & 1][1];

        float acc[3][2][4] = {};   // [mat][mfrag][reg]

        auto stageA = [&](int c, int bb) {
            const int kc0 = c * 64;
            const uint32_t dstb = sA + bb * A_SM_BYTES;
            #pragma unroll
            for (int j = 0; j < 4; j++) {
                int u = tid + j * STHREADS;
                int s = u >> 11, row = (u >> 3) & 255, kb = u & 7;
                const __nv_bfloat16* src =
                    (s ? hbf_lo : hbf_hi) + (size_t)(b0 + row) * HID + kc0 + kb * 8;
                uint32_t dst = dstb + (uint32_t)((s * 256 + row) * 128 +
                                                 ((kb * 16) ^ ((row & 7) << 4)));
                CP_ASYNC16(dst, src);
            }
        };

        stageA(0, 0);
        CP_COMMIT();
        #pragma unroll 1
        for (int c = 0; c < 4; c++) {
            if (c < 3) {
                stageA(c + 1, (c + 1) & 1);
                CP_COMMIT();
                CP_WAIT(1);
            } else {
                CP_WAIT(0);
            }
            __syncthreads();
            {
                const uint32_t Ab = sA + (c & 1) * A_SM_BYTES;
                #pragma unroll
                for (int q = 0; q < 4; q++) {
                    const uint32_t pA = (uint32_t)((q * 32 + tig * 4) ^ (group << 4));
                    uint32_t ahi[2][4], alo[2][4];
                    #pragma unroll
                    for (int f = 0; f < 2; f++) {
                        uint32_t rh = Ab + (uint32_t)((m0w + f * 16 + group) * 128) + pA;
                        ahi[f][0] = lds32(rh);        ahi[f][1] = lds32(rh + 1024);
                        ahi[f][2] = lds32(rh ^ 16u);  ahi[f][3] = lds32((rh + 1024) ^ 16u);
                        uint32_t rl = rh + 32768;
                        alo[f][0] = lds32(rl);        alo[f][1] = lds32(rl + 1024);
                        alo[f][2] = lds32(rl ^ 16u);  alo[f][3] = lds32((rl + 1024) ^ 16u);
                    }
                    const uint32_t pB = (uint32_t)((c * 128 + q * 32 + tig * 4) ^ (group << 4));
                    #pragma unroll
                    for (int mat = 0; mat < 3; mat++) {
                        uint32_t bh[2], bl[2];
                        uint32_t rbh = sW + (uint32_t)(mat * 32768) +
                                       (uint32_t)((n0w + group) * 512) + pB;
                        bh[0] = lds32(rbh);  bh[1] = lds32(rbh ^ 16u);
                        uint32_t rbl = rbh + 16384;
                        bl[0] = lds32(rbl);  bl[1] = lds32(rbl ^ 16u);
                        mma_bf16(acc[mat][0], ahi[0], bh);
                        mma_bf16(acc[mat][1], ahi[1], bh);
                        mma_bf16(acc[mat][0], ahi[0], bl);
                        mma_bf16(acc[mat][1], ahi[1], bl);
                        mma_bf16(acc[mat][0], alo[0], bh);
                        mma_bf16(acc[mat][1], alo[1], bh);
                    }
                }
            }
            __syncthreads();
        }

        // ---- fused LTC epilogue (h in registers, fast div) ----
        uint32_t* __restrict__ out_hi = (uint32_t*)g_hbf[(t + 1) & 1][0];
        uint32_t* __restrict__ out_lo = (uint32_t*)g_hbf[(t + 1) & 1][1];
        #pragma unroll
        for (int f = 0; f < 2; f++) {
            #pragma unroll
            for (int hh = 0; hh < 2; hh++) {
                const int r = m0w + f * 16 + group + hh * 8;
                const int b = b0 + r;
                const size_t hrow  = (size_t)b * HID;
                const size_t pbase = ((size_t)t * BATCH + b) * HID;
                const int jabs = n0 + n0w + tig * 2;
                float2 pf = *(const float2*)&g_proj[0][pbase + jabs];
                float2 pg = *(const float2*)&g_proj[1][pbase + jabs];
                float2 pt = *(const float2*)&g_proj[2][pbase + jabs];
                float o2[2];
                #pragma unroll
                for (int e = 0; e < 2; e++) {
                    float rf = acc[0][f][hh * 2 + e];
                    float rg = acc[1][f][hh * 2 + e];
                    float rt = acc[2][f][hh * 2 + e];
                    float pfe = e ? pf.y : pf.x;
                    float pge = e ? pg.y : pg.x;
                    float pte = e ? pt.y : pt.x;
                    float hve = hvreg[f][hh][e];
                    float e2 = __expf(2.f * (pfe + rf));
                    float cand = __fdividef(e2 - 1.f, e2 + 1.f);
                    float gate = __fdividef(1.f, 1.f + __expf(-(pge + rg)));
                    float tau  = 0.5f + 1.5f * __fdividef(1.f, 1.f + __expf(-(pte + rt)));
                    float hn = hve + __fdividef(gate * cand - hve, tau);
                    float e2h = __expf(2.f * hn);
                    o2[e] = __fdividef(e2h - 1.f, e2h + 1.f);
                    hvreg[f][hh][e] = o2[e];
                }
                *(uint32_t*)((char*)out_hi + (hrow + jabs) * 2) = pack_hi2(o2[0], o2[1]);
                *(uint32_t*)((char*)out_lo + (hrow + jabs) * 2) = pack_lo2(o2[0], o2[1]);
            }
        }

        // ---- device-wide barrier (skip after last step) ----
        if (t < T - 1) {
            __threadfence();
            __syncthreads();
            if (tid == 0) {
                unsigned need = (unsigned)(t + 1) * (unsigned)NCTA;
                unsigned arrived = atomicAdd(&g_bar_count, 1u) + 1u;
                if (arrived == need) {
                    atomicExch(&g_bar_phase, (unsigned)(t + 1));
                } else {
                    while (ldcg_u32(&g_bar_phase) < (unsigned)(t + 1)) __nanosleep(64);
                }
                __threadfence();
            }
            __syncthreads();
        }
    }
}

// ---------------- head: h reconstructed from bf16 hi/lo ----------------
__global__ void head_kernel(const float* __restrict__ hw,
                            const float* __restrict__ hb,
                            float* __restrict__ out)
{
    int gwarp = (blockIdx.x * blockDim.x + threadIdx.x) >> 5;
    int lane  = threadIdx.x & 31;
    if (gwarp >= BATCH * 10) return;
    int o = gwarp % 10;
    int b = gwarp / 10;
    const __nv_bfloat16* hhi = g_hbf[0][0];   // T=64 even -> final state parity 0
    const __nv_bfloat16* hlo = g_hbf[0][1];
    float s = 0.f;
    #pragma unroll
    for (int k = lane; k < HID; k += 32) {
        float hv = __bfloat162float(hhi[(size_t)b * HID + k]) +
                   __bfloat162float(hlo[(size_t)b * HID + k]);
        s += hv * hw[o * HID + k];
    }
    #pragma unroll
    for (int off = 16; off; off >>= 1)
        s += __shfl_down_sync(0xffffffffu, s, off);
    if (lane == 0) out[b * 10 + o] = s + hb[o];
}

extern "C" void kernel_launch(void* const* d_in, const int* in_sizes, int n_in,
                              void* d_out, int out_size)
{
    const float* x      = (const float*)d_in[0];
    const float* ffw    = (const float*)d_in[1];
    const float* ffb    = (const float*)d_in[2];
    const float* ffrw   = (const float*)d_in[3];
    const float* ffbias = (const float*)d_in[4];
    const float* gw     = (const float*)d_in[5];
    const float* gb     = (const float*)d_in[6];
    const float* grw    = (const float*)d_in[7];
    const float* gbias  = (const float*)d_in[8];
    const float* tw     = (const float*)d_in[9];
    const float* tb     = (const float*)d_in[10];
    const float* trw    = (const float*)d_in[11];
    const float* tbias  = (const float*)d_in[12];
    const float* hw     = (const float*)d_in[13];
    const float* hb     = (const float*)d_in[14];
    float* out = (float*)d_out;

    cudaFuncSetAttribute(proj_mma_kernel,
                         cudaFuncAttributeMaxDynamicSharedMemorySize, PROJ_SMEM);
    cudaFuncSetAttribute(ltc_persistent_kernel,
                         cudaFuncAttributeMaxDynamicSharedMemorySize, PERS_SMEM);

    // h0 = 0 + barrier counters reset (every replay)
    zero_h_kernel<<<(BATCH * HID + 255) / 256, 256>>>();

    // W (recurrent + input) -> bf16 hi/lo scratch
    wprep_kernel<<<(HID * HID + 255) / 256, 256>>>(ffrw, grw, trw, ffw, gw, tw);

    // all input projections on the tensor pipe (grid axes swapped for L2 reuse)
    dim3 pgrid(HID / 64, (T * BATCH) / 128);
    proj_mma_kernel<<<pgrid, NTHREADS, PROJ_SMEM>>>(x, ffb, ffbias, gb, gbias, tb, tbias);

    // all 64 LTC steps in one persistent kernel (R11 structure, best known)
    ltc_persistent_kernel<<<NCTA, STHREADS, PERS_SMEM>>>();

    // classifier head
    head_kernel<<<(BATCH * 10 * 32 + 255) / 256, 256>>>(hw, hb, out);
}

// round 14
// speedup vs baseline: 1.8673x; 1.7358x over previous
#include <cuda_runtime.h>
#include <cuda_bf16.h>
#include <cuda_fp16.h>
#include <math.h>
#include <cstdint>

#define BATCH 4096
#define T 64
#define HID 256
#define INDIM 192
#define NCTA 128

// ---------------- device scratch ----------------
__device__ float g_proj[3][(size_t)T * BATCH * HID];     // input projections (fp32)
__device__ __half g_wh[3][HID * HID];                    // W_rec fp16
__device__ __half g_wih[3][HID * INDIM];                 // W_in fp16
__device__ __half g_hh[2][BATCH * HID];                  // h fp16 ping-pong
__device__ float g_hfin[BATCH * HID];                    // final h fp32 (head input)
__device__ unsigned g_bar_count;
__device__ unsigned g_bar_phase;

// ---------------- helpers ----------------
__device__ __forceinline__ uint32_t smem_to_u32(const void* p) {
    uint32_t a;
    asm("{ .reg .u64 t; cvta.to.shared.u64 t, %1; cvt.u32.u64 %0, t; }" : "=r"(a) : "l"(p));
    return a;
}
__device__ __forceinline__ uint32_t lds32(uint32_t a) {
    uint32_t v;
    asm volatile("ld.shared.b32 %0, [%1];" : "=r"(v) : "r"(a));
    return v;
}
__device__ __forceinline__ float2 lds64f(uint32_t a) {
    float2 v;
    asm volatile("ld.shared.v2.f32 {%0, %1}, [%2];" : "=f"(v.x), "=f"(v.y) : "r"(a));
    return v;
}
__device__ __forceinline__ void sts64(uint32_t a, uint32_t v0, uint32_t v1) {
    asm volatile("st.shared.v2.b32 [%0], {%1, %2};" :: "r"(a), "r"(v0), "r"(v1));
}
__device__ __forceinline__ uint32_t ldcg_u32(const void* p) {
    uint32_t v;
    asm volatile("ld.global.cg.u32 %0, [%1];" : "=r"(v) : "l"(p));
    return v;
}
#define CP_ASYNC16(dst, src) \
    asm volatile("cp.async.cg.shared.global [%0], [%1], 16;" :: "r"(dst), "l"(src))
#define CP_COMMIT() asm volatile("cp.async.commit_group;" ::: "memory")
#define CP_WAIT(n)  asm volatile("cp.async.wait_group %0;" :: "n"(n) : "memory")

// fp16 mma: D(16x8 fp32) += A(16x16 f16) * B(16x8 f16)
__device__ __forceinline__ void mma_f16(float* c, const uint32_t* a, const uint32_t* b) {
    asm volatile(
        "mma.sync.aligned.m16n8k16.row.col.f32.f16.f16.f32 "
        "{%0,%1,%2,%3}, {%4,%5,%6,%7}, {%8,%9}, {%0,%1,%2,%3};"
        : "+f"(c[0]), "+f"(c[1]), "+f"(c[2]), "+f"(c[3])
        : "r"(a[0]), "r"(a[1]), "r"(a[2]), "r"(a[3]), "r"(b[0]), "r"(b[1]));
}

__device__ __forceinline__ uint32_t pack_f16x2(float a, float b) {
    __half2 h = __floats2half2_rn(a, b);
    return *(uint32_t*)&h;
}

// ---------------- zero h0 + barrier reset ----------------
__global__ void zero_h_kernel() {
    int i = blockIdx.x * blockDim.x + threadIdx.x;
    if (i < BATCH * HID) g_hh[0][i] = __float2half(0.f);
    if (i == 0) { g_bar_count = 0u; g_bar_phase = 0u; }
}

// ---------------- W prep: fp32 -> fp16 ----------------
__global__ void wprep_kernel(const float* __restrict__ wfr, const float* __restrict__ wgr,
                             const float* __restrict__ wtr,
                             const float* __restrict__ wfi, const float* __restrict__ wgi,
                             const float* __restrict__ wti) {
    int i = blockIdx.x * blockDim.x + threadIdx.x;
    if (i < HID * HID) {
        g_wh[0][i] = __float2half(wfr[i]);
        g_wh[1][i] = __float2half(wgr[i]);
        g_wh[2][i] = __float2half(wtr[i]);
    }
    if (i < HID * INDIM) {
        g_wih[0][i] = __float2half(wfi[i]);
        g_wih[1][i] = __float2half(wgi[i]);
        g_wih[2][i] = __float2half(wti[i]);
    }
}

// =========================================================================
// proj kernel via fp16 mma.sync (single product): 512 threads.
// grid (4 n-tiles on X for L2 x-reuse, 2048 m-tiles on Y). Tile 128m x 64n.
// =========================================================================
#define NTHREADS 512
#define PITCHB 144
#define PA_BYTES (128 * PITCHB)            // 18432
#define PB_BYTES (192 * PITCHB)            // 27648 (3 regions x 64 rows)
#define PBUF_BYTES (PA_BYTES + PB_BYTES)   // 46080
#define PROJ_SMEM (2 * PBUF_BYTES)

__global__ __launch_bounds__(NTHREADS, 1) void proj_mma_kernel(
    const float* __restrict__ x,
    const float* __restrict__ bfa, const float* __restrict__ bfb,
    const float* __restrict__ bga, const float* __restrict__ bgb,
    const float* __restrict__ bta, const float* __restrict__ btb)
{
    extern __shared__ char sm[];
    const uint32_t sbase = smem_to_u32(sm);

    const int tid   = threadIdx.x;
    const int warp  = tid >> 5;
    const int lane  = tid & 31;
    const int group = lane >> 2;
    const int tig   = lane & 3;
    const int m0    = blockIdx.y * 128;
    const int n0    = blockIdx.x * 64;
    const int m0w   = (warp & 3) * 32;
    const int n0w   = (warp >> 2) * 16;
    const int tq    = m0 >> 12;
    const int bq0   = m0 & 4095;

    float acc[3][2][2][4] = {};

    auto stageA = [&](int chunk, int bb) {
        const uint32_t dstb = sbase + bb * PBUF_BYTES;
        #pragma unroll
        for (int j = 0; j < 4; j++) {
            int u   = tid + j * NTHREADS;   // 0..2047
            int row = u >> 4;
            int f4  = u & 15;
            float4 v = *(const float4*)&x[((((size_t)(bq0 + row) * 3 + chunk) << 6) + tq) * 64 + f4 * 4];
            sts64(dstb + (uint32_t)(row * PITCHB + f4 * 8),
                  pack_f16x2(v.x, v.y), pack_f16x2(v.z, v.w));
        }
    };
    auto stageB = [&](int chunk, int bb) {
        const int kc0 = chunk * 64;
        const uint32_t dstb = sbase + bb * PBUF_BYTES + PA_BYTES;
        #pragma unroll
        for (int j = 0; j < 3; j++) {
            int u = tid + j * NTHREADS;     // 0..1535
            int mat = u >> 9, row = (u >> 3) & 63, kb = u & 7;
            const __half* src = &g_wih[mat][(size_t)(n0 + row) * INDIM + kc0 + kb * 8];
            CP_ASYNC16(dstb + (uint32_t)((mat * 64 + row) * PITCHB + kb * 16), src);
        }
    };

    auto compute = [&](int bb) {
        const uint32_t Abase = sbase + bb * PBUF_BYTES;
        const uint32_t Bbase = Abase + PA_BYTES;
        #pragma unroll
        for (int q = 0; q < 4; q++) {
            const uint32_t koff = q * 32 + tig * 4;
            uint32_t ah[2][4];
            #pragma unroll
            for (int f = 0; f < 2; f++) {
                uint32_t rh = Abase + (uint32_t)((m0w + f * 16 + group) * PITCHB) + koff;
                ah[f][0] = lds32(rh);
                ah[f][1] = lds32(rh + 8 * PITCHB);
                ah[f][2] = lds32(rh + 16);
                ah[f][3] = lds32(rh + 8 * PITCHB + 16);
            }
            #pragma unroll
            for (int mat = 0; mat < 3; mat++) {
                uint32_t bh[2][2];
                #pragma unroll
                for (int j = 0; j < 2; j++) {
                    uint32_t rbh = Bbase +
                        (uint32_t)((mat * 64 + n0w + j * 8 + group) * PITCHB) + koff;
                    bh[j][0] = lds32(rbh); bh[j][1] = lds32(rbh + 16);
                }
                #pragma unroll
                for (int j = 0; j < 2; j++) {
                    mma_f16(acc[mat][0][j], ah[0], bh[j]);
                    mma_f16(acc[mat][1][j], ah[1], bh[j]);
                }
            }
        }
    };

    stageB(0, 0); CP_COMMIT();
    stageA(0, 0);
    #pragma unroll 1
    for (int c = 0; c < 3; c++) {
        if (c < 2) {
            stageB(c + 1, (c + 1) & 1); CP_COMMIT();
            stageA(c + 1, (c + 1) & 1);
            CP_WAIT(1);
        } else {
            CP_WAIT(0);
        }
        __syncthreads();
        compute(c & 1);
        __syncthreads();
    }

    const float* inb[3]  = {bfa, bga, bta};
    const float* hbb[3]  = {bfb, bgb, btb};
    #pragma unroll
    for (int f = 0; f < 2; f++) {
        #pragma unroll
        for (int hh = 0; hh < 2; hh++) {
            const int m = m0w + f * 16 + group + hh * 8;
            const size_t obase = (size_t)(m0 + m) * HID;
            #pragma unroll
            for (int j = 0; j < 2; j++) {
                const int jabs = n0 + n0w + j * 8 + tig * 2;
                #pragma unroll
                for (int mat = 0; mat < 3; mat++) {
                    float2 bi = *(const float2*)&inb[mat][jabs];
                    float2 bh2 = *(const float2*)&hbb[mat][jabs];
                    float2 o;
                    o.x = acc[mat][f][j][hh * 2]     + bi.x + bh2.x;
                    o.y = acc[mat][f][j][hh * 2 + 1] + bi.y + bh2.y;
                    *(float2*)&g_proj[mat][obase + jabs] = o;
                }
            }
        }
    }
}

// =========================================================================
// persistent recurrence: fp16 single-product, W resident (48KB), A double-
// buffered (2x32KB), proj tile prefetched to smem (96KB).
// 128 CTAs, 1024 threads (32 warps: 8m x 4n), CTA tile 256 rows x 32 cols.
// =========================================================================
#define STHREADS 1024
#define W_SM_BYTES 49152
#define A_CH_BYTES 32768
#define P_SM_BYTES 98304
#define PERS_SMEM (W_SM_BYTES + 2 * A_CH_BYTES + P_SM_BYTES + 128)

__global__ __launch_bounds__(STHREADS, 1) void ltc_persistent_kernel()
{
    extern __shared__ char sm[];
    const uint32_t sW = (smem_to_u32(sm) + 127u) & ~127u;
    const uint32_t sA = sW + W_SM_BYTES;
    const uint32_t sP = sA + 2 * A_CH_BYTES;

    const int tid   = threadIdx.x;
    const int warp  = tid >> 5;
    const int lane  = tid & 31;
    const int group = lane >> 2;
    const int tig   = lane & 3;
    const int bx    = blockIdx.x;
    const int b0    = (bx & 15) * 256;
    const int n0    = (bx >> 4) * 32;
    const int m0w   = (warp & 7) * 32;     // 8 m-warps x 32 rows
    const int n0w   = (warp >> 3) * 8;     // 4 n-warps x 8 cols

    // ---- load W once: 3 regions x 32 rows x 512B, XOR-swizzled ----
    #pragma unroll
    for (int j = 0; j < 3; j++) {
        int u   = tid + j * STHREADS;       // 0..3071 16B units
        int rg  = u >> 10;
        int rem = u & 1023;
        int row = rem >> 5;
        int kb  = rem & 31;
        const __half* src = &g_wh[rg][(size_t)(n0 + row) * HID + kb * 8];
        CP_ASYNC16(sW + (uint32_t)(rg * 16384 + row * 512 + ((kb * 16) ^ ((row & 7) << 4))), src);
    }
    CP_COMMIT(); CP_WAIT(0);
    __syncthreads();

    // h state in registers: [f][hh][e] -> b=b0+m0w+f*16+group+hh*8, col=n0+n0w+tig*2+e
    float hvreg[2][2][2] = {};

    #pragma unroll 1
    for (int t = 0; t < T; t++) {
        const __half* __restrict__ hin = g_hh[t & 1];

        float acc[3][2][4] = {};

        auto stageA = [&](int c, int bb) {
            const int kc0 = c * 64;
            const uint32_t dstb = sA + bb * A_CH_BYTES;
            #pragma unroll
            for (int j = 0; j < 2; j++) {
                int u = tid + j * STHREADS;     // 0..2047 16B units
                int row = u >> 3, kb = u & 7;
                const __half* src = hin + (size_t)(b0 + row) * HID + kc0 + kb * 8;
                CP_ASYNC16(dstb + (uint32_t)(row * 128 + ((kb * 16) ^ ((row & 7) << 4))), src);
            }
        };
        auto stageP = [&]() {
            #pragma unroll
            for (int j = 0; j < 6; j++) {
                int u = tid + j * STHREADS;     // 0..6143 16B units
                int mat = u >> 11, row = (u >> 3) & 255, c4 = u & 7;
                const float* src = &g_proj[mat][((size_t)t * BATCH + b0 + row) * HID + n0 + c4 * 4];
                CP_ASYNC16(sP + (uint32_t)(mat * 32768 + row * 128 +
                                           ((c4 * 16) ^ ((row & 7) << 4))), src);
            }
        };

        stageA(0, 0); CP_COMMIT();           // group: A0
        stageP();     CP_COMMIT();           // group: P
        #pragma unroll 1
        for (int c = 0; c < 4; c++) {
            if (c < 3) {
                stageA(c + 1, (c + 1) & 1); CP_COMMIT();
                if (c == 0) { CP_WAIT(2); }  // A0 done; P + A1 may fly
                else        { CP_WAIT(1); }  // ... A_c done
            } else {
                CP_WAIT(0);
            }
            __syncthreads();
            {
                const uint32_t Ab = sA + (c & 1) * A_CH_BYTES;
                #pragma unroll
                for (int q = 0; q < 4; q++) {
                    const uint32_t pA = (uint32_t)((q * 32 + tig * 4) ^ (group << 4));
                    uint32_t ah[2][4];
                    #pragma unroll
                    for (int f = 0; f < 2; f++) {
                        uint32_t rh = Ab + (uint32_t)((m0w + f * 16 + group) * 128) + pA;
                        ah[f][0] = lds32(rh);        ah[f][1] = lds32(rh + 1024);
                        ah[f][2] = lds32(rh ^ 16u);  ah[f][3] = lds32((rh + 1024) ^ 16u);
                    }
                    const uint32_t pB = (uint32_t)((c * 128 + q * 32 + tig * 4) ^ (group << 4));
                    #pragma unroll
                    for (int mat = 0; mat < 3; mat++) {
                        uint32_t rbh = sW + (uint32_t)(mat * 16384) +
                                       (uint32_t)((n0w + group) * 512) + pB;
                        uint32_t bh[2] = { lds32(rbh), lds32(rbh ^ 16u) };
                        mma_f16(acc[mat][0], ah[0], bh);
                        mma_f16(acc[mat][1], ah[1], bh);
                    }
                }
            }
            __syncthreads();
        }

        // ---- fused LTC epilogue: proj from smem, h in registers ----
        __half* __restrict__ hout = g_hh[(t + 1) & 1];
        const uint32_t pcol = (uint32_t)(((n0w + tig * 2) * 4) ^ (group << 4));
        #pragma unroll
        for (int f = 0; f < 2; f++) {
            #pragma unroll
            for (int hh = 0; hh < 2; hh++) {
                const int r = m0w + f * 16 + group + hh * 8;
                const int b = b0 + r;
                const int jabs = n0 + n0w + tig * 2;
                const uint32_t prow = sP + (uint32_t)(r * 128) + pcol;
                float2 pf = lds64f(prow);
                float2 pg = lds64f(prow + 32768);
                float2 pt = lds64f(prow + 65536);
                float o2[2];
                #pragma unroll
                for (int e = 0; e < 2; e++) {
                    float rf = acc[0][f][hh * 2 + e];
                    float rg = acc[1][f][hh * 2 + e];
                    float rt = acc[2][f][hh * 2 + e];
                    float pfe = e ? pf.y : pf.x;
                    float pge = e ? pg.y : pg.x;
                    float pte = e ? pt.y : pt.x;
                    float hve = hvreg[f][hh][e];
                    float e2 = __expf(2.f * (pfe + rf));
                    float cand = __fdividef(e2 - 1.f, e2 + 1.f);
                    float gate = __fdividef(1.f, 1.f + __expf(-(pge + rg)));
                    float tau  = 0.5f + 1.5f * __fdividef(1.f, 1.f + __expf(-(pte + rt)));
                    float hn = hve + __fdividef(gate * cand - hve, tau);
                    float e2h = __expf(2.f * hn);
                    o2[e] = __fdividef(e2h - 1.f, e2h + 1.f);
                    hvreg[f][hh][e] = o2[e];
                }
                *(uint32_t*)&hout[(size_t)b * HID + jabs] = pack_f16x2(o2[0], o2[1]);
                if (t == T - 1)
                    *(float2*)&g_hfin[(size_t)b * HID + jabs] = make_float2(o2[0], o2[1]);
            }
        }

        // ---- device-wide barrier (skip after last step) ----
        if (t < T - 1) {
            __threadfence();
            __syncthreads();
            if (tid == 0) {
                unsigned need = (unsigned)(t + 1) * (unsigned)NCTA;
                unsigned arrived = atomicAdd(&g_bar_count, 1u) + 1u;
                if (arrived == need) {
                    atomicExch(&g_bar_phase, (unsigned)(t + 1));
                } else {
                    while (ldcg_u32(&g_bar_phase) < (unsigned)(t + 1)) __nanosleep(64);
                }
                __threadfence();
            }
            __syncthreads();
        }
    }
}

// ---------------- head: fp32 final h ----------------
__global__ void head_kernel(const float* __restrict__ hw,
                            const float* __restrict__ hb,
                            float* __restrict__ out)
{
    int gwarp = (blockIdx.x * blockDim.x + threadIdx.x) >> 5;
    int lane  = threadIdx.x & 31;
    if (gwarp >= BATCH * 10) return;
    int o = gwarp % 10;
    int b = gwarp / 10;
    float s = 0.f;
    #pragma unroll
    for (int k = lane; k < HID; k += 32)
        s += g_hfin[(size_t)b * HID + k] * hw[o * HID + k];
    #pragma unroll
    for (int off = 16; off; off >>= 1)
        s += __shfl_down_sync(0xffffffffu, s, off);
    if (lane == 0) out[b * 10 + o] = s + hb[o];
}

extern "C" void kernel_launch(void* const* d_in, const int* in_sizes, int n_in,
                              void* d_out, int out_size)
{
    const float* x      = (const float*)d_in[0];
    const float* ffw    = (const float*)d_in[1];
    const float* ffb    = (const float*)d_in[2];
    const float* ffrw   = (const float*)d_in[3];
    const float* ffbias = (const float*)d_in[4];
    const float* gw     = (const float*)d_in[5];
    const float* gb     = (const float*)d_in[6];
    const float* grw    = (const float*)d_in[7];
    const float* gbias  = (const float*)d_in[8];
    const float* tw     = (const float*)d_in[9];
    const float* tb     = (const float*)d_in[10];
    const float* trw    = (const float*)d_in[11];
    const float* tbias  = (const float*)d_in[12];
    const float* hw     = (const float*)d_in[13];
    const float* hb     = (const float*)d_in[14];
    float* out = (float*)d_out;

    cudaFuncSetAttribute(proj_mma_kernel,
                         cudaFuncAttributeMaxDynamicSharedMemorySize, PROJ_SMEM);
    cudaFuncSetAttribute(ltc_persistent_kernel,
                         cudaFuncAttributeMaxDynamicSharedMemorySize, PERS_SMEM);

    // h0 = 0 + barrier counters reset (every replay)
    zero_h_kernel<<<(BATCH * HID + 255) / 256, 256>>>();

    // W (recurrent + input) -> fp16 scratch
    wprep_kernel<<<(HID * HID + 255) / 256, 256>>>(ffrw, grw, trw, ffw, gw, tw);

    // all input projections (fp16 single-product mma)
    dim3 pgrid(HID / 64, (T * BATCH) / 128);
    proj_mma_kernel<<<pgrid, NTHREADS, PROJ_SMEM>>>(x, ffb, ffbias, gb, gbias, tb, tbias);

    // all 64 LTC steps in one persistent kernel (fp16, W resident, proj prefetch)
    ltc_persistent_kernel<<<NCTA, STHREADS, PERS_SMEM>>>();

    // classifier head
    head_kernel<<<(BATCH * 10 * 32 + 255) / 256, 256>>>(hw, hb, out);
}

// round 15
// speedup vs baseline: 2.0207x; 1.0822x over previous
#include <cuda_runtime.h>
#include <cuda_bf16.h>
#include <cuda_fp16.h>
#include <math.h>
#include <cstdint>

#define BATCH 4096
#define T 64
#define HID 256
#define INDIM 192
#define NCTA 128

// ---------------- device scratch ----------------
__device__ __half g_proj[3][(size_t)T * BATCH * HID];    // input projections (fp16)
__device__ __half g_wh[3][HID * HID];                    // W_rec fp16
__device__ __half g_wih[3][HID * INDIM];                 // W_in fp16
__device__ __half g_hh[2][BATCH * HID];                  // h fp16 ping-pong
__device__ float g_hfin[BATCH * HID];                    // final h fp32 (head input)
__device__ unsigned g_bar_count;
__device__ unsigned g_bar_phase;

// ---------------- helpers ----------------
__device__ __forceinline__ uint32_t smem_to_u32(const void* p) {
    uint32_t a;
    asm("{ .reg .u64 t; cvta.to.shared.u64 t, %1; cvt.u32.u64 %0, t; }" : "=r"(a) : "l"(p));
    return a;
}
__device__ __forceinline__ uint32_t lds32(uint32_t a) {
    uint32_t v;
    asm volatile("ld.shared.b32 %0, [%1];" : "=r"(v) : "r"(a));
    return v;
}
__device__ __forceinline__ void sts64(uint32_t a, uint32_t v0, uint32_t v1) {
    asm volatile("st.shared.v2.b32 [%0], {%1, %2};" :: "r"(a), "r"(v0), "r"(v1));
}
__device__ __forceinline__ uint32_t ldcg_u32(const void* p) {
    uint32_t v;
    asm volatile("ld.global.cg.u32 %0, [%1];" : "=r"(v) : "l"(p));
    return v;
}
__device__ __forceinline__ float tanhfast(float x) {
    float y;
    asm("tanh.approx.f32 %0, %1;" : "=f"(y) : "f"(x));
    return y;
}
#define CP_ASYNC16(dst, src) \
    asm volatile("cp.async.cg.shared.global [%0], [%1], 16;" :: "r"(dst), "l"(src))
#define CP_COMMIT() asm volatile("cp.async.commit_group;" ::: "memory")
#define CP_WAIT(n)  asm volatile("cp.async.wait_group %0;" :: "n"(n) : "memory")

// fp16 mma: D(16x8 fp32) += A(16x16 f16) * B(16x8 f16)
__device__ __forceinline__ void mma_f16(float* c, const uint32_t* a, const uint32_t* b) {
    asm volatile(
        "mma.sync.aligned.m16n8k16.row.col.f32.f16.f16.f32 "
        "{%0,%1,%2,%3}, {%4,%5,%6,%7}, {%8,%9}, {%0,%1,%2,%3};"
        : "+f"(c[0]), "+f"(c[1]), "+f"(c[2]), "+f"(c[3])
        : "r"(a[0]), "r"(a[1]), "r"(a[2]), "r"(a[3]), "r"(b[0]), "r"(b[1]));
}

__device__ __forceinline__ uint32_t pack_f16x2(float a, float b) {
    __half2 h = __floats2half2_rn(a, b);
    return *(uint32_t*)&h;
}

// ---------------- zero h0 + barrier reset ----------------
__global__ void zero_h_kernel() {
    int i = blockIdx.x * blockDim.x + threadIdx.x;
    if (i < BATCH * HID) g_hh[0][i] = __float2half(0.f);
    if (i == 0) { g_bar_count = 0u; g_bar_phase = 0u; }
}

// ---------------- W prep: fp32 -> fp16 ----------------
__global__ void wprep_kernel(const float* __restrict__ wfr, const float* __restrict__ wgr,
                             const float* __restrict__ wtr,
                             const float* __restrict__ wfi, const float* __restrict__ wgi,
                             const float* __restrict__ wti) {
    int i = blockIdx.x * blockDim.x + threadIdx.x;
    if (i < HID * HID) {
        g_wh[0][i] = __float2half(wfr[i]);
        g_wh[1][i] = __float2half(wgr[i]);
        g_wh[2][i] = __float2half(wtr[i]);
    }
    if (i < HID * INDIM) {
        g_wih[0][i] = __float2half(wfi[i]);
        g_wih[1][i] = __float2half(wgi[i]);
        g_wih[2][i] = __float2half(wti[i]);
    }
}

// =========================================================================
// proj kernel via fp16 mma.sync: 512 threads, fp16 output.
// grid (4 n-tiles on X for L2 x-reuse, 2048 m-tiles on Y). Tile 128m x 64n.
// =========================================================================
#define NTHREADS 512
#define PITCHB 144
#define PA_BYTES (128 * PITCHB)
#define PB_BYTES (192 * PITCHB)
#define PBUF_BYTES (PA_BYTES + PB_BYTES)
#define PROJ_SMEM (2 * PBUF_BYTES)

__global__ __launch_bounds__(NTHREADS, 1) void proj_mma_kernel(
    const float* __restrict__ x,
    const float* __restrict__ bfa, const float* __restrict__ bfb,
    const float* __restrict__ bga, const float* __restrict__ bgb,
    const float* __restrict__ bta, const float* __restrict__ btb)
{
    extern __shared__ char sm[];
    const uint32_t sbase = smem_to_u32(sm);

    const int tid   = threadIdx.x;
    const int warp  = tid >> 5;
    const int lane  = tid & 31;
    const int group = lane >> 2;
    const int tig   = lane & 3;
    const int m0    = blockIdx.y * 128;
    const int n0    = blockIdx.x * 64;
    const int m0w   = (warp & 3) * 32;
    const int n0w   = (warp >> 2) * 16;
    const int tq    = m0 >> 12;
    const int bq0   = m0 & 4095;

    float acc[3][2][2][4] = {};

    auto stageA = [&](int chunk, int bb) {
        const uint32_t dstb = sbase + bb * PBUF_BYTES;
        #pragma unroll
        for (int j = 0; j < 4; j++) {
            int u   = tid + j * NTHREADS;
            int row = u >> 4;
            int f4  = u & 15;
            float4 v = *(const float4*)&x[((((size_t)(bq0 + row) * 3 + chunk) << 6) + tq) * 64 + f4 * 4];
            sts64(dstb + (uint32_t)(row * PITCHB + f4 * 8),
                  pack_f16x2(v.x, v.y), pack_f16x2(v.z, v.w));
        }
    };
    auto stageB = [&](int chunk, int bb) {
        const int kc0 = chunk * 64;
        const uint32_t dstb = sbase + bb * PBUF_BYTES + PA_BYTES;
        #pragma unroll
        for (int j = 0; j < 3; j++) {
            int u = tid + j * NTHREADS;
            int mat = u >> 9, row = (u >> 3) & 63, kb = u & 7;
            const __half* src = &g_wih[mat][(size_t)(n0 + row) * INDIM + kc0 + kb * 8];
            CP_ASYNC16(dstb + (uint32_t)((mat * 64 + row) * PITCHB + kb * 16), src);
        }
    };

    auto compute = [&](int bb) {
        const uint32_t Abase = sbase + bb * PBUF_BYTES;
        const uint32_t Bbase = Abase + PA_BYTES;
        #pragma unroll
        for (int q = 0; q < 4; q++) {
            const uint32_t koff = q * 32 + tig * 4;
            uint32_t ah[2][4];
            #pragma unroll
            for (int f = 0; f < 2; f++) {
                uint32_t rh = Abase + (uint32_t)((m0w + f * 16 + group) * PITCHB) + koff;
                ah[f][0] = lds32(rh);
                ah[f][1] = lds32(rh + 8 * PITCHB);
                ah[f][2] = lds32(rh + 16);
                ah[f][3] = lds32(rh + 8 * PITCHB + 16);
            }
            #pragma unroll
            for (int mat = 0; mat < 3; mat++) {
                uint32_t bh[2][2];
                #pragma unroll
                for (int j = 0; j < 2; j++) {
                    uint32_t rbh = Bbase +
                        (uint32_t)((mat * 64 + n0w + j * 8 + group) * PITCHB) + koff;
                    bh[j][0] = lds32(rbh); bh[j][1] = lds32(rbh + 16);
                }
                #pragma unroll
                for (int j = 0; j < 2; j++) {
                    mma_f16(acc[mat][0][j], ah[0], bh[j]);
                    mma_f16(acc[mat][1][j], ah[1], bh[j]);
                }
            }
        }
    };

    stageB(0, 0); CP_COMMIT();
    stageA(0, 0);
    #pragma unroll 1
    for (int c = 0; c < 3; c++) {
        if (c < 2) {
            stageB(c + 1, (c + 1) & 1); CP_COMMIT();
            stageA(c + 1, (c + 1) & 1);
            CP_WAIT(1);
        } else {
            CP_WAIT(0);
        }
        __syncthreads();
        compute(c & 1);
        __syncthreads();
    }

    const float* inb[3]  = {bfa, bga, bta};
    const float* hbb[3]  = {bfb, bgb, btb};
    #pragma unroll
    for (int f = 0; f < 2; f++) {
        #pragma unroll
        for (int hh = 0; hh < 2; hh++) {
            const int m = m0w + f * 16 + group + hh * 8;
            const size_t obase = (size_t)(m0 + m) * HID;
            #pragma unroll
            for (int j = 0; j < 2; j++) {
                const int jabs = n0 + n0w + j * 8 + tig * 2;
                #pragma unroll
                for (int mat = 0; mat < 3; mat++) {
                    float2 bi = *(const float2*)&inb[mat][jabs];
                    float2 bh2 = *(const float2*)&hbb[mat][jabs];
                    float ox = acc[mat][f][j][hh * 2]     + bi.x + bh2.x;
                    float oy = acc[mat][f][j][hh * 2 + 1] + bi.y + bh2.y;
                    *(uint32_t*)&g_proj[mat][obase + jabs] = pack_f16x2(ox, oy);
                }
            }
        }
    }
}

// =========================================================================
// persistent recurrence: fp16, W resident (48KB), A double-buffered (2x32KB),
// fp16 proj tile prefetched to smem (60KB, pitch 80 = conflict-free).
// 128 CTAs, 1024 threads (32 warps: 8m x 4n), CTA tile 256 rows x 32 cols.
// =========================================================================
#define STHREADS 1024
#define W_SM_BYTES 49152
#define A_CH_BYTES 32768
#define P_PITCH 80
#define P_MAT_BYTES (256 * P_PITCH)            // 20480
#define P_SM_BYTES (3 * P_MAT_BYTES)           // 61440
#define PERS_SMEM (W_SM_BYTES + 2 * A_CH_BYTES + P_SM_BYTES + 128)

__global__ __launch_bounds__(STHREADS, 1) void ltc_persistent_kernel()
{
    extern __shared__ char sm[];
    const uint32_t sW = (smem_to_u32(sm) + 127u) & ~127u;
    const uint32_t sA = sW + W_SM_BYTES;
    const uint32_t sP = sA + 2 * A_CH_BYTES;

    const int tid   = threadIdx.x;
    const int warp  = tid >> 5;
    const int lane  = tid & 31;
    const int group = lane >> 2;
    const int tig   = lane & 3;
    const int bx    = blockIdx.x;
    const int b0    = (bx & 15) * 256;
    const int n0    = (bx >> 4) * 32;
    const int m0w   = (warp & 7) * 32;     // 8 m-warps x 32 rows
    const int n0w   = (warp >> 3) * 8;     // 4 n-warps x 8 cols

    // ---- load W once: 3 regions x 32 rows x 512B, XOR-swizzled ----
    #pragma unroll
    for (int j = 0; j < 3; j++) {
        int u   = tid + j * STHREADS;
        int rg  = u >> 10;
        int rem = u & 1023;
        int row = rem >> 5;
        int kb  = rem & 31;
        const __half* src = &g_wh[rg][(size_t)(n0 + row) * HID + kb * 8];
        CP_ASYNC16(sW + (uint32_t)(rg * 16384 + row * 512 + ((kb * 16) ^ ((row & 7) << 4))), src);
    }
    CP_COMMIT(); CP_WAIT(0);
    __syncthreads();

    // h state in registers: [f][hh][e] -> b=b0+m0w+f*16+group+hh*8, col=n0+n0w+tig*2+e
    float hvreg[2][2][2] = {};

    #pragma unroll 1
    for (int t = 0; t < T; t++) {
        const __half* __restrict__ hin = g_hh[t & 1];

        float acc[3][2][4] = {};

        auto stageA = [&](int c, int bb) {
            const int kc0 = c * 64;
            const uint32_t dstb = sA + bb * A_CH_BYTES;
            #pragma unroll
            for (int j = 0; j < 2; j++) {
                int u = tid + j * STHREADS;
                int row = u >> 3, kb = u & 7;
                const __half* src = hin + (size_t)(b0 + row) * HID + kc0 + kb * 8;
                CP_ASYNC16(dstb + (uint32_t)(row * 128 + ((kb * 16) ^ ((row & 7) << 4))), src);
            }
        };
        auto stageP = [&]() {
            #pragma unroll
            for (int j = 0; j < 3; j++) {
                int u = tid + j * STHREADS;     // 0..3071 16B units
                int mat = u >> 10, rem = u & 1023;
                int row = rem >> 2, unit = rem & 3;
                const __half* src =
                    &g_proj[mat][((size_t)t * BATCH + b0 + row) * HID + n0 + unit * 8];
                CP_ASYNC16(sP + (uint32_t)(mat * P_MAT_BYTES + row * P_PITCH + unit * 16), src);
            }
        };

        stageA(0, 0); CP_COMMIT();           // group: A0
        stageP();     CP_COMMIT();           // group: P
        #pragma unroll 1
        for (int c = 0; c < 4; c++) {
            if (c < 3) {
                stageA(c + 1, (c + 1) & 1); CP_COMMIT();
                if (c == 0) { CP_WAIT(2); }  // A0 done; P + A1 may fly
                else        { CP_WAIT(1); }
            } else {
                CP_WAIT(0);
            }
            __syncthreads();
            {
                const uint32_t Ab = sA + (c & 1) * A_CH_BYTES;
                #pragma unroll
                for (int q = 0; q < 4; q++) {
                    const uint32_t pA = (uint32_t)((q * 32 + tig * 4) ^ (group << 4));
                    uint32_t ah[2][4];
                    #pragma unroll
                    for (int f = 0; f < 2; f++) {
                        uint32_t rh = Ab + (uint32_t)((m0w + f * 16 + group) * 128) + pA;
                        ah[f][0] = lds32(rh);        ah[f][1] = lds32(rh + 1024);
                        ah[f][2] = lds32(rh ^ 16u);  ah[f][3] = lds32((rh + 1024) ^ 16u);
                    }
                    const uint32_t pB = (uint32_t)((c * 128 + q * 32 + tig * 4) ^ (group << 4));
                    #pragma unroll
                    for (int mat = 0; mat < 3; mat++) {
                        uint32_t rbh = sW + (uint32_t)(mat * 16384) +
                                       (uint32_t)((n0w + group) * 512) + pB;
                        uint32_t bh[2] = { lds32(rbh), lds32(rbh ^ 16u) };
                        mma_f16(acc[mat][0], ah[0], bh);
                        mma_f16(acc[mat][1], ah[1], bh);
                    }
                }
            }
            __syncthreads();
        }

        // ---- fused LTC epilogue: fp16 proj from smem, MUFU.TANH, h in regs ----
        __half* __restrict__ hout = g_hh[(t + 1) & 1];
        const uint32_t pcol = (uint32_t)((n0w >> 3) * 16 + tig * 4);
        #pragma unroll
        for (int f = 0; f < 2; f++) {
            #pragma unroll
            for (int hh = 0; hh < 2; hh++) {
                const int r = m0w + f * 16 + group + hh * 8;
                const int b = b0 + r;
                const int jabs = n0 + n0w + tig * 2;
                const uint32_t prow = sP + (uint32_t)(r * P_PITCH) + pcol;
                uint32_t pfu = lds32(prow);
                uint32_t pgu = lds32(prow + P_MAT_BYTES);
                uint32_t ptu = lds32(prow + 2 * P_MAT_BYTES);
                float2 pf = __half22float2(*(__half2*)&pfu);
                float2 pg = __half22float2(*(__half2*)&pgu);
                float2 pt = __half22float2(*(__half2*)&ptu);
                float o2[2];
                #pragma unroll
                for (int e = 0; e < 2; e++) {
                    float rf = acc[0][f][hh * 2 + e];
                    float rg = acc[1][f][hh * 2 + e];
                    float rt = acc[2][f][hh * 2 + e];
                    float pfe = e ? pf.y : pf.x;
                    float pge = e ? pg.y : pg.x;
                    float pte = e ? pt.y : pt.x;
                    float hve = hvreg[f][hh][e];
                    float cand = tanhfast(pfe + rf);
                    float gate = 0.5f * tanhfast(0.5f * (pge + rg)) + 0.5f;
                    float tau  = 1.25f + 0.75f * tanhfast(0.5f * (pte + rt));
                    float hn = hve + __fdividef(gate * cand - hve, tau);
                    o2[e] = tanhfast(hn);
                    hvreg[f][hh][e] = o2[e];
                }
                *(uint32_t*)&hout[(size_t)b * HID + jabs] = pack_f16x2(o2[0], o2[1]);
                if (t == T - 1)
                    *(float2*)&g_hfin[(size_t)b * HID + jabs] = make_float2(o2[0], o2[1]);
            }
        }

        // ---- device-wide barrier (skip after last step) ----
        if (t < T - 1) {
            __threadfence();
            __syncthreads();
            if (tid == 0) {
                unsigned need = (unsigned)(t + 1) * (unsigned)NCTA;
                unsigned arrived = atomicAdd(&g_bar_count, 1u) + 1u;
                if (arrived == need) {
                    atomicExch(&g_bar_phase, (unsigned)(t + 1));
                } else {
                    while (ldcg_u32(&g_bar_phase) < (unsigned)(t + 1)) __nanosleep(64);
                }
                __threadfence();
            }
            __syncthreads();
        }
    }
}

// ---------------- head: fp32 final h ----------------
__global__ void head_kernel(const float* __restrict__ hw,
                            const float* __restrict__ hb,
                            float* __restrict__ out)
{
    int gwarp = (blockIdx.x * blockDim.x + threadIdx.x) >> 5;
    int lane  = threadIdx.x & 31;
    if (gwarp >= BATCH * 10) return;
    int o = gwarp % 10;
    int b = gwarp / 10;
    float s = 0.f;
    #pragma unroll
    for (int k = lane; k < HID; k += 32)
        s += g_hfin[(size_t)b * HID + k] * hw[o * HID + k];
    #pragma unroll
    for (int off = 16; off; off >>= 1)
        s += __shfl_down_sync(0xffffffffu, s, off);
    if (lane == 0) out[b * 10 + o] = s + hb[o];
}

extern "C" void kernel_launch(void* const* d_in, const int* in_sizes, int n_in,
                              void* d_out, int out_size)
{
    const float* x      = (const float*)d_in[0];
    const float* ffw    = (const float*)d_in[1];
    const float* ffb    = (const float*)d_in[2];
    const float* ffrw   = (const float*)d_in[3];
    const float* ffbias = (const float*)d_in[4];
    const float* gw     = (const float*)d_in[5];
    const float* gb     = (const float*)d_in[6];
    const float* grw    = (const float*)d_in[7];
    const float* gbias  = (const float*)d_in[8];
    const float* tw     = (const float*)d_in[9];
    const float* tb     = (const float*)d_in[10];
    const float* trw    = (const float*)d_in[11];
    const float* tbias  = (const float*)d_in[12];
    const float* hw     = (const float*)d_in[13];
    const float* hb     = (const float*)d_in[14];
    float* out = (float*)d_out;

    cudaFuncSetAttribute(proj_mma_kernel,
                         cudaFuncAttributeMaxDynamicSharedMemorySize, PROJ_SMEM);
    cudaFuncSetAttribute(ltc_persistent_kernel,
                         cudaFuncAttributeMaxDynamicSharedMemorySize, PERS_SMEM);

    // h0 = 0 + barrier counters reset (every replay)
    zero_h_kernel<<<(BATCH * HID + 255) / 256, 256>>>();

    // W (recurrent + input) -> fp16 scratch
    wprep_kernel<<<(HID * HID + 255) / 256, 256>>>(ffrw, grw, trw, ffw, gw, tw);

    // all input projections (fp16 mma, fp16 output)
    dim3 pgrid(HID / 64, (T * BATCH) / 128);
    proj_mma_kernel<<<pgrid, NTHREADS, PROJ_SMEM>>>(x, ffb, ffbias, gb, gbias, tb, tbias);

    // all 64 LTC steps (fp16, W resident, fp16 proj prefetch, MUFU.TANH)
    ltc_persistent_kernel<<<NCTA, STHREADS, PERS_SMEM>>>();

    // classifier head
    head_kernel<<<(BATCH * 10 * 32 + 255) / 256, 256>>>(hw, hb, out);
}

// round 16
// speedup vs baseline: 2.1327x; 1.0554x over previous
#include <cuda_runtime.h>
#include <cuda_bf16.h>
#include <cuda_fp16.h>
#include <math.h>
#include <cstdint>

#define BATCH 4096
#define T 64
#define HID 256
#define INDIM 192
#define NCTA 128

// ---------------- device scratch ----------------
__device__ __half g_proj[3][(size_t)T * BATCH * HID];    // input projections (fp16)
__device__ __half g_xh[(size_t)T * BATCH * INDIM];       // x in fp16, seq-major [t*B+b][i]
__device__ __half g_wh[3][HID * HID];                    // W_rec fp16
__device__ __half g_wih[3][HID * INDIM];                 // W_in fp16
__device__ __half g_hh[2][BATCH * HID];                  // h fp16 ping-pong
__device__ float g_hfin[BATCH * HID];                    // final h fp32 (head input)
__device__ unsigned g_bar_count[16][32];                 // per-b-group barrier (padded)
__device__ unsigned g_bar_phase[16][32];

// ---------------- helpers ----------------
__device__ __forceinline__ uint32_t smem_to_u32(const void* p) {
    uint32_t a;
    asm("{ .reg .u64 t; cvta.to.shared.u64 t, %1; cvt.u32.u64 %0, t; }" : "=r"(a) : "l"(p));
    return a;
}
__device__ __forceinline__ uint32_t lds32(uint32_t a) {
    uint32_t v;
    asm volatile("ld.shared.b32 %0, [%1];" : "=r"(v) : "r"(a));
    return v;
}
__device__ __forceinline__ uint32_t ldcg_u32(const void* p) {
    uint32_t v;
    asm volatile("ld.global.cg.u32 %0, [%1];" : "=r"(v) : "l"(p));
    return v;
}
__device__ __forceinline__ float tanhfast(float x) {
    float y;
    asm("tanh.approx.f32 %0, %1;" : "=f"(y) : "f"(x));
    return y;
}
#define CP_ASYNC16(dst, src) \
    asm volatile("cp.async.cg.shared.global [%0], [%1], 16;" :: "r"(dst), "l"(src))
#define CP_COMMIT() asm volatile("cp.async.commit_group;" ::: "memory")
#define CP_WAIT(n)  asm volatile("cp.async.wait_group %0;" :: "n"(n) : "memory")

// fp16 mma: D(16x8 fp32) += A(16x16 f16) * B(16x8 f16)
__device__ __forceinline__ void mma_f16(float* c, const uint32_t* a, const uint32_t* b) {
    asm volatile(
        "mma.sync.aligned.m16n8k16.row.col.f32.f16.f16.f32 "
        "{%0,%1,%2,%3}, {%4,%5,%6,%7}, {%8,%9}, {%0,%1,%2,%3};"
        : "+f"(c[0]), "+f"(c[1]), "+f"(c[2]), "+f"(c[3])
        : "r"(a[0]), "r"(a[1]), "r"(a[2]), "r"(a[3]), "r"(b[0]), "r"(b[1]));
}

__device__ __forceinline__ uint32_t pack_f16x2(float a, float b) {
    __half2 h = __floats2half2_rn(a, b);
    return *(uint32_t*)&h;
}

// ---------------- zero h0 + barrier reset ----------------
__global__ void zero_h_kernel() {
    int i = blockIdx.x * blockDim.x + threadIdx.x;
    if (i < BATCH * HID) g_hh[0][i] = __float2half(0.f);
    if (i < 16) { g_bar_count[i][0] = 0u; g_bar_phase[i][0] = 0u; }
}

// ---------------- W prep: fp32 -> fp16 ----------------
__global__ void wprep_kernel(const float* __restrict__ wfr, const float* __restrict__ wgr,
                             const float* __restrict__ wtr,
                             const float* __restrict__ wfi, const float* __restrict__ wgi,
                             const float* __restrict__ wti) {
    int i = blockIdx.x * blockDim.x + threadIdx.x;
    if (i < HID * HID) {
        g_wh[0][i] = __float2half(wfr[i]);
        g_wh[1][i] = __float2half(wgr[i]);
        g_wh[2][i] = __float2half(wtr[i]);
    }
    if (i < HID * INDIM) {
        g_wih[0][i] = __float2half(wfi[i]);
        g_wih[1][i] = __float2half(wgi[i]);
        g_wih[2][i] = __float2half(wti[i]);
    }
}

// ---------------- x prep: fp32 NCHW-ish -> fp16 seq-major [m=t*B+b][i] ----------------
__global__ void xprep_kernel(const float* __restrict__ x) {
    size_t idx = ((size_t)blockIdx.x * blockDim.x + threadIdx.x) * 4;
    if (idx >= (size_t)T * BATCH * INDIM) return;
    int i = (int)(idx % INDIM);
    size_t m = idx / INDIM;
    int b = (int)(m & 4095);
    int t = (int)(m >> 12);
    int ch = i >> 6, w = i & 63;
    float4 v = *(const float4*)&x[((size_t)(b * 3 + ch) * 64 + t) * 64 + w];
    uint2 o;
    o.x = pack_f16x2(v.x, v.y);
    o.y = pack_f16x2(v.z, v.w);
    *(uint2*)&g_xh[m * INDIM + i] = o;
}

// =========================================================================
// proj kernel: B-resident m-loop. grid (4 n-tiles on X, 128 m-groups on Y),
// 1024 threads, each block: load W_in once (83KB), loop 16 m-tiles of 128
// rows with double-buffered cp.async A staging from g_xh.
// warp layout: 32 warps = 4m x 8n; per-warp tile 32 rows x 8 cols x 3 mats.
// =========================================================================
#define PTHREADS 1024
#define PITCHB 144
#define PJ_ACH 18432                       // 128 rows * PITCHB (one 64-col chunk)
#define PJ_A (3 * PJ_ACH)                  // 55296 per buffer
#define PJ_BCH 27648                       // 3 mats * 64 rows * PITCHB
#define PJ_B (3 * PJ_BCH)                  // 82944
#define PROJ_SMEM (2 * PJ_A + PJ_B + 128)  // 193664
#define MTILES 16

__global__ __launch_bounds__(PTHREADS, 1) void proj_mma_kernel(
    const float* __restrict__ bfa, const float* __restrict__ bfb,
    const float* __restrict__ bga, const float* __restrict__ bgb,
    const float* __restrict__ bta, const float* __restrict__ btb)
{
    extern __shared__ char sm[];
    const uint32_t sbase = (smem_to_u32(sm) + 127u) & ~127u;
    const uint32_t sB    = sbase + 2 * PJ_A;

    const int tid   = threadIdx.x;
    const int warp  = tid >> 5;
    const int lane  = tid & 31;
    const int group = lane >> 2;
    const int tig   = lane & 3;
    const int n0    = blockIdx.x * 64;
    const int mg0   = blockIdx.y * MTILES;   // first m-tile of this block
    const int m0w   = (warp & 3) * 32;
    const int n0w   = (warp >> 2) * 8;

    // ---- stage W_in once: 3 chunks x 3 mats x 64 rows x 8 units ----
    #pragma unroll
    for (int j = 0; j < 5; j++) {
        int u = tid + j * PTHREADS;
        if (u < 4608) {
            int chunk = u / 1536, rem = u % 1536;
            int mat = rem >> 9, row = (rem >> 3) & 63, kb = rem & 7;
            const __half* src = &g_wih[mat][(size_t)(n0 + row) * INDIM + chunk * 64 + kb * 8];
            CP_ASYNC16(sB + (uint32_t)(chunk * PJ_BCH + (mat * 64 + row) * PITCHB + kb * 16), src);
        }
    }

    // ---- A staging: one m-tile (128 rows x 192 cols fp16) = 3072 16B units ----
    auto stageA = [&](int mt, int bb) {
        const size_t mrow0 = (size_t)(mg0 + mt) * 128;
        const uint32_t dstb = sbase + bb * PJ_A;
        #pragma unroll
        for (int j = 0; j < 3; j++) {
            int u = tid + j * PTHREADS;         // 0..3071
            int chunk = u >> 10, rem = u & 1023;
            int row = rem >> 3, kb = rem & 7;
            const __half* src = &g_xh[(mrow0 + row) * INDIM + chunk * 64 + kb * 8];
            CP_ASYNC16(dstb + (uint32_t)(chunk * PJ_ACH + row * PITCHB + kb * 16), src);
        }
    };

    stageA(0, 0);
    CP_COMMIT();

    // hoisted biases for this thread's columns
    const int jabs = n0 + n0w + tig * 2;
    float2 bsum[3];
    {
        const float* a0[3] = {bfa, bga, bta};
        const float* a1[3] = {bfb, bgb, btb};
        #pragma unroll
        for (int mat = 0; mat < 3; mat++) {
            float2 u = *(const float2*)&a0[mat][jabs];
            float2 v = *(const float2*)&a1[mat][jabs];
            bsum[mat] = make_float2(u.x + v.x, u.y + v.y);
        }
    }

    #pragma unroll 1
    for (int mt = 0; mt < MTILES; mt++) {
        if (mt + 1 < MTILES) {
            stageA(mt + 1, (mt + 1) & 1);
            CP_COMMIT();
            CP_WAIT(1);
        } else {
            CP_WAIT(0);
        }
        __syncthreads();

        float acc[3][2][4] = {};
        const uint32_t Ab = sbase + (mt & 1) * PJ_A;
        #pragma unroll
        for (int c = 0; c < 3; c++) {
            #pragma unroll
            for (int q = 0; q < 4; q++) {
                const uint32_t koff = q * 32 + tig * 4;
                uint32_t ah[2][4];
                #pragma unroll
                for (int f = 0; f < 2; f++) {
                    uint32_t rh = Ab + (uint32_t)(c * PJ_ACH +
                                  (m0w + f * 16 + group) * PITCHB) + koff;
                    ah[f][0] = lds32(rh);
                    ah[f][1] = lds32(rh + 8 * PITCHB);
                    ah[f][2] = lds32(rh + 16);
                    ah[f][3] = lds32(rh + 8 * PITCHB + 16);
                }
                #pragma unroll
                for (int mat = 0; mat < 3; mat++) {
                    uint32_t rbh = sB + (uint32_t)(c * PJ_BCH +
                                   (mat * 64 + n0w + group) * PITCHB) + koff;
                    uint32_t bh[2] = { lds32(rbh), lds32(rbh + 16) };
                    mma_f16(acc[mat][0], ah[0], bh);
                    mma_f16(acc[mat][1], ah[1], bh);
                }
            }
        }

        // epilogue: bias + fp16 store
        const size_t mrow0 = (size_t)(mg0 + mt) * 128;
        #pragma unroll
        for (int f = 0; f < 2; f++) {
            #pragma unroll
            for (int hh = 0; hh < 2; hh++) {
                const int r = m0w + f * 16 + group + hh * 8;
                const size_t obase = (mrow0 + r) * HID;
                #pragma unroll
                for (int mat = 0; mat < 3; mat++) {
                    float ox = acc[mat][f][hh * 2]     + bsum[mat].x;
                    float oy = acc[mat][f][hh * 2 + 1] + bsum[mat].y;
                    *(uint32_t*)&g_proj[mat][obase + jabs] = pack_f16x2(ox, oy);
                }
            }
        }
        __syncthreads();
    }
}

// =========================================================================
// persistent recurrence: fp16, W resident (48KB), A double-buffered (2x32KB),
// fp16 proj tile prefetched (60KB). Per-b-group (8 CTA) barriers.
// 128 CTAs, 1024 threads (32 warps: 8m x 4n), CTA tile 256 rows x 32 cols.
// =========================================================================
#define STHREADS 1024
#define W_SM_BYTES 49152
#define A_CH_BYTES 32768
#define P_PITCH 80
#define P_MAT_BYTES (256 * P_PITCH)
#define P_SM_BYTES (3 * P_MAT_BYTES)
#define PERS_SMEM (W_SM_BYTES + 2 * A_CH_BYTES + P_SM_BYTES + 128)

__global__ __launch_bounds__(STHREADS, 1) void ltc_persistent_kernel()
{
    extern __shared__ char sm[];
    const uint32_t sW = (smem_to_u32(sm) + 127u) & ~127u;
    const uint32_t sA = sW + W_SM_BYTES;
    const uint32_t sP = sA + 2 * A_CH_BYTES;

    const int tid   = threadIdx.x;
    const int warp  = tid >> 5;
    const int lane  = tid & 31;
    const int group = lane >> 2;
    const int tig   = lane & 3;
    const int bx    = blockIdx.x;
    const int grp   = bx & 15;
    const int b0    = grp * 256;
    const int n0    = (bx >> 4) * 32;
    const int m0w   = (warp & 7) * 32;
    const int n0w   = (warp >> 3) * 8;

    // ---- load W once ----
    #pragma unroll
    for (int j = 0; j < 3; j++) {
        int u   = tid + j * STHREADS;
        int rg  = u >> 10;
        int rem = u & 1023;
        int row = rem >> 5;
        int kb  = rem & 31;
        const __half* src = &g_wh[rg][(size_t)(n0 + row) * HID + kb * 8];
        CP_ASYNC16(sW + (uint32_t)(rg * 16384 + row * 512 + ((kb * 16) ^ ((row & 7) << 4))), src);
    }
    CP_COMMIT(); CP_WAIT(0);
    __syncthreads();

    float hvreg[2][2][2] = {};

    #pragma unroll 1
    for (int t = 0; t < T; t++) {
        const __half* __restrict__ hin = g_hh[t & 1];

        float acc[3][2][4] = {};

        auto stageA = [&](int c, int bb) {
            const int kc0 = c * 64;
            const uint32_t dstb = sA + bb * A_CH_BYTES;
            #pragma unroll
            for (int j = 0; j < 2; j++) {
                int u = tid + j * STHREADS;
                int row = u >> 3, kb = u & 7;
                const __half* src = hin + (size_t)(b0 + row) * HID + kc0 + kb * 8;
                CP_ASYNC16(dstb + (uint32_t)(row * 128 + ((kb * 16) ^ ((row & 7) << 4))), src);
            }
        };
        auto stageP = [&]() {
            #pragma unroll
            for (int j = 0; j < 3; j++) {
                int u = tid + j * STHREADS;
                int mat = u >> 10, rem = u & 1023;
                int row = rem >> 2, unit = rem & 3;
                const __half* src =
                    &g_proj[mat][((size_t)t * BATCH + b0 + row) * HID + n0 + unit * 8];
                CP_ASYNC16(sP + (uint32_t)(mat * P_MAT_BYTES + row * P_PITCH + unit * 16), src);
            }
        };

        stageA(0, 0); CP_COMMIT();
        stageP();     CP_COMMIT();
        #pragma unroll 1
        for (int c = 0; c < 4; c++) {
            if (c < 3) {
                stageA(c + 1, (c + 1) & 1); CP_COMMIT();
                if (c == 0) { CP_WAIT(2); }
                else        { CP_WAIT(1); }
            } else {
                CP_WAIT(0);
            }
            __syncthreads();
            {
                const uint32_t Ab = sA + (c & 1) * A_CH_BYTES;
                #pragma unroll
                for (int q = 0; q < 4; q++) {
                    const uint32_t pA = (uint32_t)((q * 32 + tig * 4) ^ (group << 4));
                    uint32_t ah[2][4];
                    #pragma unroll
                    for (int f = 0; f < 2; f++) {
                        uint32_t rh = Ab + (uint32_t)((m0w + f * 16 + group) * 128) + pA;
                        ah[f][0] = lds32(rh);        ah[f][1] = lds32(rh + 1024);
                        ah[f][2] = lds32(rh ^ 16u);  ah[f][3] = lds32((rh + 1024) ^ 16u);
                    }
                    const uint32_t pB = (uint32_t)((c * 128 + q * 32 + tig * 4) ^ (group << 4));
                    #pragma unroll
                    for (int mat = 0; mat < 3; mat++) {
                        uint32_t rbh = sW + (uint32_t)(mat * 16384) +
                                       (uint32_t)((n0w + group) * 512) + pB;
                        uint32_t bh[2] = { lds32(rbh), lds32(rbh ^ 16u) };
                        mma_f16(acc[mat][0], ah[0], bh);
                        mma_f16(acc[mat][1], ah[1], bh);
                    }
                }
            }
            __syncthreads();
        }

        // ---- fused LTC epilogue ----
        __half* __restrict__ hout = g_hh[(t + 1) & 1];
        const uint32_t pcol = (uint32_t)((n0w >> 3) * 16 + tig * 4);
        #pragma unroll
        for (int f = 0; f < 2; f++) {
            #pragma unroll
            for (int hh = 0; hh < 2; hh++) {
                const int r = m0w + f * 16 + group + hh * 8;
                const int b = b0 + r;
                const int jabs = n0 + n0w + tig * 2;
                const uint32_t prow = sP + (uint32_t)(r * P_PITCH) + pcol;
                uint32_t pfu = lds32(prow);
                uint32_t pgu = lds32(prow + P_MAT_BYTES);
                uint32_t ptu = lds32(prow + 2 * P_MAT_BYTES);
                float2 pf = __half22float2(*(__half2*)&pfu);
                float2 pg = __half22float2(*(__half2*)&pgu);
                float2 pt = __half22float2(*(__half2*)&ptu);
                float o2[2];
                #pragma unroll
                for (int e = 0; e < 2; e++) {
                    float rf = acc[0][f][hh * 2 + e];
                    float rg = acc[1][f][hh * 2 + e];
                    float rt = acc[2][f][hh * 2 + e];
                    float pfe = e ? pf.y : pf.x;
                    float pge = e ? pg.y : pg.x;
                    float pte = e ? pt.y : pt.x;
                    float hve = hvreg[f][hh][e];
                    float cand = tanhfast(pfe + rf);
                    float gate = 0.5f * tanhfast(0.5f * (pge + rg)) + 0.5f;
                    float tau  = 1.25f + 0.75f * tanhfast(0.5f * (pte + rt));
                    float hn = hve + __fdividef(gate * cand - hve, tau);
                    o2[e] = tanhfast(hn);
                    hvreg[f][hh][e] = o2[e];
                }
                *(uint32_t*)&hout[(size_t)b * HID + jabs] = pack_f16x2(o2[0], o2[1]);
                if (t == T - 1)
                    *(float2*)&g_hfin[(size_t)b * HID + jabs] = make_float2(o2[0], o2[1]);
            }
        }

        // ---- per-b-group barrier (8 CTAs; skip after last step) ----
        if (t < T - 1) {
            __threadfence();
            __syncthreads();
            if (tid == 0) {
                unsigned need = (unsigned)(t + 1) * 8u;
                unsigned arrived = atomicAdd(&g_bar_count[grp][0], 1u) + 1u;
                if (arrived == need) {
                    atomicExch(&g_bar_phase[grp][0], (unsigned)(t + 1));
                } else {
                    while (ldcg_u32(&g_bar_phase[grp][0]) < (unsigned)(t + 1)) __nanosleep(64);
                }
                __threadfence();
            }
            __syncthreads();
        }
    }
}

// ---------------- head: fp32 final h ----------------
__global__ void head_kernel(const float* __restrict__ hw,
                            const float* __restrict__ hb,
                            float* __restrict__ out)
{
    int gwarp = (blockIdx.x * blockDim.x + threadIdx.x) >> 5;
    int lane  = threadIdx.x & 31;
    if (gwarp >= BATCH * 10) return;
    int o = gwarp % 10;
    int b = gwarp / 10;
    float s = 0.f;
    #pragma unroll
    for (int k = lane; k < HID; k += 32)
        s += g_hfin[(size_t)b * HID + k] * hw[o * HID + k];
    #pragma unroll
    for (int off = 16; off; off >>= 1)
        s += __shfl_down_sync(0xffffffffu, s, off);
    if (lane == 0) out[b * 10 + o] = s + hb[o];
}

extern "C" void kernel_launch(void* const* d_in, const int* in_sizes, int n_in,
                              void* d_out, int out_size)
{
    const float* x      = (const float*)d_in[0];
    const float* ffw    = (const float*)d_in[1];
    const float* ffb    = (const float*)d_in[2];
    const float* ffrw   = (const float*)d_in[3];
    const float* ffbias = (const float*)d_in[4];
    const float* gw     = (const float*)d_in[5];
    const float* gb     = (const float*)d_in[6];
    const float* grw    = (const float*)d_in[7];
    const float* gbias  = (const float*)d_in[8];
    const float* tw     = (const float*)d_in[9];
    const float* tb     = (const float*)d_in[10];
    const float* trw    = (const float*)d_in[11];
    const float* tbias  = (const float*)d_in[12];
    const float* hw     = (const float*)d_in[13];
    const float* hb     = (const float*)d_in[14];
    float* out = (float*)d_out;

    cudaFuncSetAttribute(proj_mma_kernel,
                         cudaFuncAttributeMaxDynamicSharedMemorySize, PROJ_SMEM);
    cudaFuncSetAttribute(ltc_persistent_kernel,
                         cudaFuncAttributeMaxDynamicSharedMemorySize, PERS_SMEM);

    // h0 = 0 + barrier counters reset (every replay)
    zero_h_kernel<<<(BATCH * HID + 255) / 256, 256>>>();

    // W -> fp16; x -> fp16 seq-major
    wprep_kernel<<<(HID * HID + 255) / 256, 256>>>(ffrw, grw, trw, ffw, gw, tw);
    xprep_kernel<<<(int)(((size_t)T * BATCH * INDIM / 4 + 255) / 256), 256>>>(x);

    // input projections: B-resident m-loop (4 n-tiles x 128 m-groups)
    dim3 pgrid(HID / 64, (T * BATCH) / 128 / MTILES);
    proj_mma_kernel<<<pgrid, PTHREADS, PROJ_SMEM>>>(ffb, ffbias, gb, gbias, tb, tbias);

    // all 64 LTC steps (fp16, W resident, per-group barriers)
    ltc_persistent_kernel<<<NCTA, STHREADS, PERS_SMEM>>>();

    // classifier head
    head_kernel<<<(BATCH * 10 * 32 + 255) / 256, 256>>>(hw, hb, out);
}

// round 17
// speedup vs baseline: 2.3117x; 1.0839x over previous
#include <cuda_runtime.h>
#include <cuda_bf16.h>
#include <cuda_fp16.h>
#include <math.h>
#include <cstdint>

#define BATCH 4096
#define T 64
#define HID 256
#define INDIM 192
#define NCTA 128

// ---------------- device scratch ----------------
__device__ __half g_proj[3][(size_t)T * BATCH * HID];    // input projections (fp16)
__device__ __half g_xh[(size_t)T * BATCH * INDIM];       // x in fp16, seq-major [t*B+b][i]
__device__ __half g_wh[3][HID * HID];                    // W_rec fp16
__device__ __half g_wih[3][HID * INDIM];                 // W_in fp16
__device__ __half g_hh[2][BATCH * HID];                  // h fp16 ping-pong
__device__ float g_hfin[BATCH * HID];                    // final h fp32 (head input)
__device__ unsigned g_bar_count[16][32];                 // per-b-group barrier (padded)
__device__ unsigned g_bar_phase[16][32];

// ---------------- helpers ----------------
__device__ __forceinline__ uint32_t smem_to_u32(const void* p) {
    uint32_t a;
    asm("{ .reg .u64 t; cvta.to.shared.u64 t, %1; cvt.u32.u64 %0, t; }" : "=r"(a) : "l"(p));
    return a;
}
__device__ __forceinline__ uint32_t lds32(uint32_t a) {
    uint32_t v;
    asm volatile("ld.shared.b32 %0, [%1];" : "=r"(v) : "r"(a));
    return v;
}
__device__ __forceinline__ uint32_t ldcg_u32(const void* p) {
    uint32_t v;
    asm volatile("ld.global.cg.u32 %0, [%1];" : "=r"(v) : "l"(p));
    return v;
}
__device__ __forceinline__ float tanhfast(float x) {
    float y;
    asm("tanh.approx.f32 %0, %1;" : "=f"(y) : "f"(x));
    return y;
}
#define CP_ASYNC16(dst, src) \
    asm volatile("cp.async.cg.shared.global [%0], [%1], 16;" :: "r"(dst), "l"(src))
#define CP_COMMIT() asm volatile("cp.async.commit_group;" ::: "memory")
#define CP_WAIT(n)  asm volatile("cp.async.wait_group %0;" :: "n"(n) : "memory")

// fp16 mma: D(16x8 fp32) += A(16x16 f16) * B(16x8 f16)
__device__ __forceinline__ void mma_f16(float* c, const uint32_t* a, const uint32_t* b) {
    asm volatile(
        "mma.sync.aligned.m16n8k16.row.col.f32.f16.f16.f32 "
        "{%0,%1,%2,%3}, {%4,%5,%6,%7}, {%8,%9}, {%0,%1,%2,%3};"
        : "+f"(c[0]), "+f"(c[1]), "+f"(c[2]), "+f"(c[3])
        : "r"(a[0]), "r"(a[1]), "r"(a[2]), "r"(a[3]), "r"(b[0]), "r"(b[1]));
}

__device__ __forceinline__ uint32_t pack_f16x2(float a, float b) {
    __half2 h = __floats2half2_rn(a, b);
    return *(uint32_t*)&h;
}

// ---------------- W prep: fp32 -> fp16 ----------------
__global__ void wprep_kernel(const float* __restrict__ wfr, const float* __restrict__ wgr,
                             const float* __restrict__ wtr,
                             const float* __restrict__ wfi, const float* __restrict__ wgi,
                             const float* __restrict__ wti) {
    int i = blockIdx.x * blockDim.x + threadIdx.x;
    if (i < HID * HID) {
        g_wh[0][i] = __float2half(wfr[i]);
        g_wh[1][i] = __float2half(wgr[i]);
        g_wh[2][i] = __float2half(wtr[i]);
    }
    if (i < HID * INDIM) {
        g_wih[0][i] = __float2half(wfi[i]);
        g_wih[1][i] = __float2half(wgi[i]);
        g_wih[2][i] = __float2half(wti[i]);
    }
}

// ---------------- x prep (+ h0 zero + barrier reset fused) ----------------
__global__ void xprep_kernel(const float* __restrict__ x) {
    size_t gtid = (size_t)blockIdx.x * blockDim.x + threadIdx.x;
    size_t idx = gtid * 4;
    if (idx < (size_t)T * BATCH * INDIM) {
        int i = (int)(idx % INDIM);
        size_t m = idx / INDIM;
        int b = (int)(m & 4095);
        int t = (int)(m >> 12);
        int ch = i >> 6, w = i & 63;
        float4 v = *(const float4*)&x[((size_t)(b * 3 + ch) * 64 + t) * 64 + w];
        uint2 o;
        o.x = pack_f16x2(v.x, v.y);
        o.y = pack_f16x2(v.z, v.w);
        *(uint2*)&g_xh[m * INDIM + i] = o;
    }
    if (gtid < BATCH * HID / 2)
        *(uint32_t*)&g_hh[0][gtid * 2] = 0u;
    if (gtid < 16) { g_bar_count[gtid][0] = 0u; g_bar_phase[gtid][0] = 0u; }
}

// =========================================================================
// proj kernel (unchanged from R16): B-resident m-loop, 1024 threads,
// grid (4 n-tiles on X, 128 m-groups on Y).
// =========================================================================
#define PTHREADS 1024
#define PITCHB 144
#define PJ_ACH 18432
#define PJ_A (3 * PJ_ACH)
#define PJ_BCH 27648
#define PJ_B (3 * PJ_BCH)
#define PROJ_SMEM (2 * PJ_A + PJ_B + 128)
#define MTILES 16

__global__ __launch_bounds__(PTHREADS, 1) void proj_mma_kernel(
    const float* __restrict__ bfa, const float* __restrict__ bfb,
    const float* __restrict__ bga, const float* __restrict__ bgb,
    const float* __restrict__ bta, const float* __restrict__ btb)
{
    extern __shared__ char sm[];
    const uint32_t sbase = (smem_to_u32(sm) + 127u) & ~127u;
    const uint32_t sB    = sbase + 2 * PJ_A;

    const int tid   = threadIdx.x;
    const int warp  = tid >> 5;
    const int lane  = tid & 31;
    const int group = lane >> 2;
    const int tig   = lane & 3;
    const int n0    = blockIdx.x * 64;
    const int mg0   = blockIdx.y * MTILES;
    const int m0w   = (warp & 3) * 32;
    const int n0w   = (warp >> 2) * 8;

    #pragma unroll
    for (int j = 0; j < 5; j++) {
        int u = tid + j * PTHREADS;
        if (u < 4608) {
            int chunk = u / 1536, rem = u % 1536;
            int mat = rem >> 9, row = (rem >> 3) & 63, kb = rem & 7;
            const __half* src = &g_wih[mat][(size_t)(n0 + row) * INDIM + chunk * 64 + kb * 8];
            CP_ASYNC16(sB + (uint32_t)(chunk * PJ_BCH + (mat * 64 + row) * PITCHB + kb * 16), src);
        }
    }

    auto stageA = [&](int mt, int bb) {
        const size_t mrow0 = (size_t)(mg0 + mt) * 128;
        const uint32_t dstb = sbase + bb * PJ_A;
        #pragma unroll
        for (int j = 0; j < 3; j++) {
            int u = tid + j * PTHREADS;
            int chunk = u >> 10, rem = u & 1023;
            int row = rem >> 3, kb = rem & 7;
            const __half* src = &g_xh[(mrow0 + row) * INDIM + chunk * 64 + kb * 8];
            CP_ASYNC16(dstb + (uint32_t)(chunk * PJ_ACH + row * PITCHB + kb * 16), src);
        }
    };

    stageA(0, 0);
    CP_COMMIT();

    const int jabs = n0 + n0w + tig * 2;
    float2 bsum[3];
    {
        const float* a0[3] = {bfa, bga, bta};
        const float* a1[3] = {bfb, bgb, btb};
        #pragma unroll
        for (int mat = 0; mat < 3; mat++) {
            float2 u = *(const float2*)&a0[mat][jabs];
            float2 v = *(const float2*)&a1[mat][jabs];
            bsum[mat] = make_float2(u.x + v.x, u.y + v.y);
        }
    }

    #pragma unroll 1
    for (int mt = 0; mt < MTILES; mt++) {
        if (mt + 1 < MTILES) {
            stageA(mt + 1, (mt + 1) & 1);
            CP_COMMIT();
            CP_WAIT(1);
        } else {
            CP_WAIT(0);
        }
        __syncthreads();

        float acc[3][2][4] = {};
        const uint32_t Ab = sbase + (mt & 1) * PJ_A;
        #pragma unroll
        for (int c = 0; c < 3; c++) {
            #pragma unroll
            for (int q = 0; q < 4; q++) {
                const uint32_t koff = q * 32 + tig * 4;
                uint32_t ah[2][4];
                #pragma unroll
                for (int f = 0; f < 2; f++) {
                    uint32_t rh = Ab + (uint32_t)(c * PJ_ACH +
                                  (m0w + f * 16 + group) * PITCHB) + koff;
                    ah[f][0] = lds32(rh);
                    ah[f][1] = lds32(rh + 8 * PITCHB);
                    ah[f][2] = lds32(rh + 16);
                    ah[f][3] = lds32(rh + 8 * PITCHB + 16);
                }
                #pragma unroll
                for (int mat = 0; mat < 3; mat++) {
                    uint32_t rbh = sB + (uint32_t)(c * PJ_BCH +
                                   (mat * 64 + n0w + group) * PITCHB) + koff;
                    uint32_t bh[2] = { lds32(rbh), lds32(rbh + 16) };
                    mma_f16(acc[mat][0], ah[0], bh);
                    mma_f16(acc[mat][1], ah[1], bh);
                }
            }
        }

        const size_t mrow0 = (size_t)(mg0 + mt) * 128;
        #pragma unroll
        for (int f = 0; f < 2; f++) {
            #pragma unroll
            for (int hh = 0; hh < 2; hh++) {
                const int r = m0w + f * 16 + group + hh * 8;
                const size_t obase = (mrow0 + r) * HID;
                #pragma unroll
                for (int mat = 0; mat < 3; mat++) {
                    float ox = acc[mat][f][hh * 2]     + bsum[mat].x;
                    float oy = acc[mat][f][hh * 2 + 1] + bsum[mat].y;
                    *(uint32_t*)&g_proj[mat][obase + jabs] = pack_f16x2(ox, oy);
                }
            }
        }
        __syncthreads();
    }
}

// =========================================================================
// persistent recurrence: fp16, W resident (48KB), A double-buffered 2x64KB
// (K chunks of 128), P tile 48KB (pitch 64). 2 syncs + 2 waits per step.
// 128 CTAs, 1024 threads (32 warps: 8m x 4n), CTA tile 256 rows x 32 cols.
// =========================================================================
#define STHREADS 1024
#define W_SM_BYTES 49152
#define A_CH_BYTES 65536               // 256 rows x 256B (k=128 chunk)
#define P_PITCH 64
#define P_MAT_BYTES (256 * P_PITCH)    // 16384
#define P_SM_BYTES (3 * P_MAT_BYTES)   // 49152
#define PERS_SMEM (W_SM_BYTES + 2 * A_CH_BYTES + P_SM_BYTES + 128)  // 229504

__global__ __launch_bounds__(STHREADS, 1) void ltc_persistent_kernel()
{
    extern __shared__ char sm[];
    const uint32_t sW = (smem_to_u32(sm) + 127u) & ~127u;
    const uint32_t sA = sW + W_SM_BYTES;
    const uint32_t sP = sA + 2 * A_CH_BYTES;

    const int tid   = threadIdx.x;
    const int warp  = tid >> 5;
    const int lane  = tid & 31;
    const int group = lane >> 2;
    const int tig   = lane & 3;
    const int bx    = blockIdx.x;
    const int grp   = bx & 15;
    const int b0    = grp * 256;
    const int n0    = (bx >> 4) * 32;
    const int m0w   = (warp & 7) * 32;
    const int n0w   = (warp >> 3) * 8;

    // ---- load W once: 3 regions x 32 rows x 512B, XOR-swizzled ----
    #pragma unroll
    for (int j = 0; j < 3; j++) {
        int u   = tid + j * STHREADS;
        int rg  = u >> 10;
        int rem = u & 1023;
        int row = rem >> 5;
        int kb  = rem & 31;
        const __half* src = &g_wh[rg][(size_t)(n0 + row) * HID + kb * 8];
        CP_ASYNC16(sW + (uint32_t)(rg * 16384 + row * 512 + ((kb * 16) ^ ((row & 7) << 4))), src);
    }
    CP_COMMIT(); CP_WAIT(0);
    __syncthreads();

    float hvreg[2][2][2] = {};

    #pragma unroll 1
    for (int t = 0; t < T; t++) {
        const __half* __restrict__ hin = g_hh[t & 1];

        float acc[3][2][4] = {};

        // stage one 128-wide K chunk of A (256 rows): 4096 16B units
        auto stageA = [&](int c, int bb) {
            const int kc0 = c * 128;
            const uint32_t dstb = sA + bb * A_CH_BYTES;
            #pragma unroll
            for (int j = 0; j < 4; j++) {
                int u = tid + j * STHREADS;
                int row = u >> 4, kb = u & 15;
                const __half* src = hin + (size_t)(b0 + row) * HID + kc0 + kb * 8;
                CP_ASYNC16(dstb + (uint32_t)(row * 256 + ((kb * 16) ^ ((row & 7) << 4))), src);
            }
        };
        auto stageP = [&]() {
            #pragma unroll
            for (int j = 0; j < 3; j++) {
                int u = tid + j * STHREADS;
                int mat = u >> 10, rem = u & 1023;
                int row = rem >> 2, unit = rem & 3;
                const __half* src =
                    &g_proj[mat][((size_t)t * BATCH + b0 + row) * HID + n0 + unit * 8];
                CP_ASYNC16(sP + (uint32_t)(mat * P_MAT_BYTES + row * P_PITCH + unit * 16), src);
            }
        };

        stageA(0, 0); CP_COMMIT();
        stageP();     CP_COMMIT();
        stageA(1, 1); CP_COMMIT();

        #pragma unroll 1
        for (int c = 0; c < 2; c++) {
            if (c == 0) { CP_WAIT(2); }     // A0 landed; P + A1 in flight
            else        { CP_WAIT(0); }     // everything landed
            __syncthreads();
            const uint32_t Ab = sA + c * A_CH_BYTES;
            #pragma unroll
            for (int q = 0; q < 8; q++) {
                const uint32_t pA = (uint32_t)((q * 32 + tig * 4) ^ (group << 4));
                uint32_t ah[2][4];
                #pragma unroll
                for (int f = 0; f < 2; f++) {
                    uint32_t rh = Ab + (uint32_t)((m0w + f * 16 + group) * 256) + pA;
                    ah[f][0] = lds32(rh);        ah[f][1] = lds32(rh + 2048);
                    ah[f][2] = lds32(rh ^ 16u);  ah[f][3] = lds32((rh + 2048) ^ 16u);
                }
                const uint32_t pB = (uint32_t)((c * 256 + q * 32 + tig * 4) ^ (group << 4));
                #pragma unroll
                for (int mat = 0; mat < 3; mat++) {
                    uint32_t rbh = sW + (uint32_t)(mat * 16384) +
                                   (uint32_t)((n0w + group) * 512) + pB;
                    uint32_t bh[2] = { lds32(rbh), lds32(rbh ^ 16u) };
                    mma_f16(acc[mat][0], ah[0], bh);
                    mma_f16(acc[mat][1], ah[1], bh);
                }
            }
        }

        // ---- fused LTC epilogue (P in smem since CP_WAIT(0)+sync) ----
        __half* __restrict__ hout = g_hh[(t + 1) & 1];
        const uint32_t pcol = (uint32_t)((n0w >> 3) * 16 + tig * 4);
        #pragma unroll
        for (int f = 0; f < 2; f++) {
            #pragma unroll
            for (int hh = 0; hh < 2; hh++) {
                const int r = m0w + f * 16 + group + hh * 8;
                const int b = b0 + r;
                const int jabs = n0 + n0w + tig * 2;
                const uint32_t prow = sP + (uint32_t)(r * P_PITCH) + pcol;
                uint32_t pfu = lds32(prow);
                uint32_t pgu = lds32(prow + P_MAT_BYTES);
                uint32_t ptu = lds32(prow + 2 * P_MAT_BYTES);
                float2 pf = __half22float2(*(__half2*)&pfu);
                float2 pg = __half22float2(*(__half2*)&pgu);
                float2 pt = __half22float2(*(__half2*)&ptu);
                float o2[2];
                #pragma unroll
                for (int e = 0; e < 2; e++) {
                    float rf = acc[0][f][hh * 2 + e];
                    float rg = acc[1][f][hh * 2 + e];
                    float rt = acc[2][f][hh * 2 + e];
                    float pfe = e ? pf.y : pf.x;
                    float pge = e ? pg.y : pg.x;
                    float pte = e ? pt.y : pt.x;
                    float hve = hvreg[f][hh][e];
                    float cand = tanhfast(pfe + rf);
                    float gate = 0.5f * tanhfast(0.5f * (pge + rg)) + 0.5f;
                    float tau  = 1.25f + 0.75f * tanhfast(0.5f * (pte + rt));
                    float hn = hve + __fdividef(gate * cand - hve, tau);
                    o2[e] = tanhfast(hn);
                    hvreg[f][hh][e] = o2[e];
                }
                *(uint32_t*)&hout[(size_t)b * HID + jabs] = pack_f16x2(o2[0], o2[1]);
                if (t == T - 1)
                    *(float2*)&g_hfin[(size_t)b * HID + jabs] = make_float2(o2[0], o2[1]);
            }
        }

        // ---- per-b-group barrier (8 CTAs; skip after last step) ----
        if (t < T - 1) {
            __threadfence();
            __syncthreads();
            if (tid == 0) {
                unsigned need = (unsigned)(t + 1) * 8u;
                unsigned arrived = atomicAdd(&g_bar_count[grp][0], 1u) + 1u;
                if (arrived == need) {
                    atomicExch(&g_bar_phase[grp][0], (unsigned)(t + 1));
                } else {
                    while (ldcg_u32(&g_bar_phase[grp][0]) < (unsigned)(t + 1)) __nanosleep(64);
                }
                __threadfence();
            }
            __syncthreads();
        }
    }
}

// ---------------- head: fp32 final h ----------------
__global__ void head_kernel(const float* __restrict__ hw,
                            const float* __restrict__ hb,
                            float* __restrict__ out)
{
    int gwarp = (blockIdx.x * blockDim.x + threadIdx.x) >> 5;
    int lane  = threadIdx.x & 31;
    if (gwarp >= BATCH * 10) return;
    int o = gwarp % 10;
    int b = gwarp / 10;
    float s = 0.f;
    #pragma unroll
    for (int k = lane; k < HID; k += 32)
        s += g_hfin[(size_t)b * HID + k] * hw[o * HID + k];
    #pragma unroll
    for (int off = 16; off; off >>= 1)
        s += __shfl_down_sync(0xffffffffu, s, off);
    if (lane == 0) out[b * 10 + o] = s + hb[o];
}

extern "C" void kernel_launch(void* const* d_in, const int* in_sizes, int n_in,
                              void* d_out, int out_size)
{
    const float* x      = (const float*)d_in[0];
    const float* ffw    = (const float*)d_in[1];
    const float* ffb    = (const float*)d_in[2];
    const float* ffrw   = (const float*)d_in[3];
    const float* ffbias = (const float*)d_in[4];
    const float* gw     = (const float*)d_in[5];
    const float* gb     = (const float*)d_in[6];
    const float* grw    = (const float*)d_in[7];
    const float* gbias  = (const float*)d_in[8];
    const float* tw     = (const float*)d_in[9];
    const float* tb     = (const float*)d_in[10];
    const float* trw    = (const float*)d_in[11];
    const float* tbias  = (const float*)d_in[12];
    const float* hw     = (const float*)d_in[13];
    const float* hb     = (const float*)d_in[14];
    float* out = (float*)d_out;

    cudaFuncSetAttribute(proj_mma_kernel,
                         cudaFuncAttributeMaxDynamicSharedMemorySize, PROJ_SMEM);
    cudaFuncSetAttribute(ltc_persistent_kernel,
                         cudaFuncAttributeMaxDynamicSharedMemorySize, PERS_SMEM);

    // W -> fp16; x -> fp16 seq-major (+ h0 zero + barrier reset fused)
    wprep_kernel<<<(HID * HID + 255) / 256, 256>>>(ffrw, grw, trw, ffw, gw, tw);
    xprep_kernel<<<(int)(((size_t)T * BATCH * INDIM / 4 + 255) / 256), 256>>>(x);

    // input projections: B-resident m-loop (4 n-tiles x 128 m-groups)
    dim3 pgrid(HID / 64, (T * BATCH) / 128 / MTILES);
    proj_mma_kernel<<<pgrid, PTHREADS, PROJ_SMEM>>>(ffb, ffbias, gb, gbias, tb, tbias);

    // all 64 LTC steps (fp16, W resident, 2x128 K chunks, per-group barriers)
    ltc_persistent_kernel<<<NCTA, STHREADS, PERS_SMEM>>>();

    // classifier head
    head_kernel<<<(BATCH * 10 * 32 + 255) / 256, 256>>>(hw, hb, out);
}